// round 11
// baseline (speedup 1.0000x reference)
#include <cuda_runtime.h>
#include <cuda_bf16.h>
#include <cstdint>

#define B_  4
#define S_  2048
#define D_  1024
#define H_  16
#define HD_ 64

// ---------------------------------------------------------------------------
// Static scratch (bf16 hi/lo split form everywhere), 16B-aligned for cp.async
// ---------------------------------------------------------------------------
__device__ __align__(16) __nv_bfloat16 g_xh[3][B_ * S_ * D_], g_xl[3][B_ * S_ * D_];
__device__ __align__(16) __nv_bfloat16 g_wh[3][H_ * D_ * HD_], g_wl[3][H_ * D_ * HD_];
__device__ __align__(16) __nv_bfloat16 g_woh[D_ * D_], g_wol[D_ * D_];
__device__ __align__(16) __nv_bfloat16 g_qh[B_*H_*S_*HD_], g_ql[B_*H_*S_*HD_];
__device__ __align__(16) __nv_bfloat16 g_kh[B_*H_*S_*HD_], g_kl[B_*H_*S_*HD_];
__device__ __align__(16) __nv_bfloat16 g_vh[B_*H_*S_*HD_], g_vl[B_*H_*S_*HD_];
__device__ __align__(16) __nv_bfloat16 g_zh[B_ * S_ * D_], g_zl[B_ * S_ * D_];
__device__ unsigned g_mpk[B_ * S_ * (S_ / 32)];

// ---------------------------------------------------------------------------
// Helpers
// ---------------------------------------------------------------------------
__device__ __forceinline__ uint32_t pack2(float x, float y) {
    __nv_bfloat162 t = __floats2bfloat162_rn(x, y);
    return *reinterpret_cast<uint32_t*>(&t);
}
__device__ __forceinline__ void split_pack(float x, float y, uint32_t& hi, uint32_t& lo) {
    float hx = __bfloat162float(__float2bfloat16(x));
    float hy = __bfloat162float(__float2bfloat16(y));
    hi = pack2(hx, hy);
    lo = pack2(x - hx, y - hy);
}
__device__ __forceinline__ float ex2(float x) {
    float y; asm("ex2.approx.f32 %0, %1;" : "=f"(y) : "f"(x)); return y;
}
__device__ __forceinline__ uint32_t smem_u32(const void* p) {
    return (uint32_t)__cvta_generic_to_shared(p);
}
__device__ __forceinline__ void ldsm4(uint32_t r[4], uint32_t a) {
    asm volatile("ldmatrix.sync.aligned.m8n8.x4.shared.b16 {%0,%1,%2,%3}, [%4];"
                 : "=r"(r[0]), "=r"(r[1]), "=r"(r[2]), "=r"(r[3]) : "r"(a));
}
__device__ __forceinline__ void ldsm4t(uint32_t r[4], uint32_t a) {
    asm volatile("ldmatrix.sync.aligned.m8n8.x4.trans.shared.b16 {%0,%1,%2,%3}, [%4];"
                 : "=r"(r[0]), "=r"(r[1]), "=r"(r[2]), "=r"(r[3]) : "r"(a));
}
__device__ __forceinline__ void mma_bf16(float c[4], const uint32_t a[4], const uint32_t b[2]) {
    asm volatile(
        "mma.sync.aligned.m16n8k16.row.col.f32.bf16.bf16.f32 "
        "{%0,%1,%2,%3}, {%4,%5,%6,%7}, {%8,%9}, {%0,%1,%2,%3};\n"
        : "+f"(c[0]), "+f"(c[1]), "+f"(c[2]), "+f"(c[3])
        : "r"(a[0]), "r"(a[1]), "r"(a[2]), "r"(a[3]), "r"(b[0]), "r"(b[1]));
}
__device__ __forceinline__ void cpa16(uint32_t saddr, const void* g) {
    asm volatile("cp.async.cg.shared.global [%0], [%1], 16;" :: "r"(saddr), "l"(g) : "memory");
}
__device__ __forceinline__ void cpa_commit() { asm volatile("cp.async.commit_group;" ::: "memory"); }
__device__ __forceinline__ void cpa_wait0()  { asm volatile("cp.async.wait_group 0;" ::: "memory"); }
__device__ __forceinline__ void cpa_wait1()  { asm volatile("cp.async.wait_group 1;" ::: "memory"); }
__device__ __forceinline__ void cpa_wait2()  { asm volatile("cp.async.wait_group 2;" ::: "memory"); }

// ---------------------------------------------------------------------------
// Fused split kernels
// ---------------------------------------------------------------------------
__global__ void split_x_kernel(const float* __restrict__ xq, const float* __restrict__ xk,
                               const float* __restrict__ xv)
{
    const int which = blockIdx.x >> 13;
    const int i = (blockIdx.x & 8191) * 256 + threadIdx.x;
    const float* in = (which == 0) ? xq : (which == 1) ? xk : xv;
    float4 v = ((const float4*)in)[i];
    uint32_t h0, l0, h1, l1;
    split_pack(v.x, v.y, h0, l0);
    split_pack(v.z, v.w, h1, l1);
    ((uint2*)g_xh[which])[i] = make_uint2(h0, h1);
    ((uint2*)g_xl[which])[i] = make_uint2(l0, l1);
}

__global__ void split_w_kernel(const float* __restrict__ Wq, const float* __restrict__ Wk,
                               const float* __restrict__ Wv, const float* __restrict__ Wo)
{
    const int dst = blockIdx.x >> 10;
    const int i = (blockIdx.x & 1023) * 256 + threadIdx.x;
    const float* in = (dst == 0) ? Wq : (dst == 1) ? Wk : (dst == 2) ? Wv : Wo;
    __nv_bfloat16* hi = (dst < 3) ? g_wh[dst] : g_woh;
    __nv_bfloat16* lo = (dst < 3) ? g_wl[dst] : g_wol;
    float4 v = ((const float4*)in)[i];
    uint32_t h0, l0, h1, l1;
    split_pack(v.x, v.y, h0, l0);
    split_pack(v.z, v.w, h1, l1);
    ((uint2*)hi)[i] = make_uint2(h0, h1);
    ((uint2*)lo)[i] = make_uint2(l0, l1);
}

__global__ void pack_mask_kernel(const int* __restrict__ mask)
{
    int i = blockIdx.x * 256 + threadIdx.x;
    if (i >= B_ * S_ * (S_ / 32)) return;
    const int4* mp = (const int4*)(mask + (long)i * 32);
    unsigned w = 0;
#pragma unroll
    for (int j = 0; j < 8; j++) {
        int4 m = mp[j];
        w |= (unsigned)(m.x != 0) << (j * 4 + 0);
        w |= (unsigned)(m.y != 0) << (j * 4 + 1);
        w |= (unsigned)(m.z != 0) << (j * 4 + 2);
        w |= (unsigned)(m.w != 0) << (j * 4 + 3);
    }
    g_mpk[i] = w;
}

// ---------------------------------------------------------------------------
// GEMM: 128(m) x 128(n) x kdim, k-chunks of 32, 3-stage cp.async pipeline.
// ---------------------------------------------------------------------------
#define G_STG   37888
#define G_AL    10240
#define G_BH    20480
#define G_BL    29184
#define GEMM_DSM (3 * G_STG)

template<bool SPLIT_OUT>
__device__ __forceinline__ void gemm_body(
    const __nv_bfloat16* __restrict__ Agh, const __nv_bfloat16* __restrict__ Agl,
    int lda, int kdim,
    const __nv_bfloat16* __restrict__ Bgh, const __nv_bfloat16* __restrict__ Bgl,
    long bHS, int ldb,
    const float* __restrict__ bias,
    float* __restrict__ outF, int ldoF,
    __nv_bfloat16* __restrict__ outH, __nv_bfloat16* __restrict__ outL, long outHS)
{
    extern __shared__ uint8_t dyn[];
    const uint32_t sb = smem_u32(dyn);

    const int t = threadIdx.x, lane = t & 31, warp = t >> 5;
    const int wm = warp >> 1, wn = warp & 1;
    const int lr = lane >> 2, lc = lane & 3;
    const int g = lane >> 3, lr8 = lane & 7;

    float c[2][8][4];
#pragma unroll
    for (int i = 0; i < 2; i++)
#pragma unroll
        for (int j = 0; j < 8; j++)
#pragma unroll
            for (int k = 0; k < 4; k++) c[i][j][k] = 0.f;

#define G_ISSUE(stg, k0) do { \
        uint32_t base_ = sb + (stg) * G_STG; \
        _Pragma("unroll") \
        for (int j = 0; j < 2; j++) { \
            int idx = t + j * 256, r = idx >> 2, cc = idx & 3; \
            cpa16(base_ + r * 80 + cc * 16,         Agh + (long)r * lda + (k0) + cc * 8); \
            cpa16(base_ + G_AL + r * 80 + cc * 16,  Agl + (long)r * lda + (k0) + cc * 8); \
        } \
        _Pragma("unroll") \
        for (int j = 0; j < 2; j++) { \
            int idx = t + j * 256, r = idx >> 4, n16 = idx & 15; \
            long src = (long)(n16 >> 3) * bHS + (long)((k0) + r) * ldb + (n16 & 7) * 8; \
            cpa16(base_ + G_BH + r * 272 + n16 * 16, Bgh + src); \
            cpa16(base_ + G_BL + r * 272 + n16 * 16, Bgl + src); \
        } \
        cpa_commit(); \
    } while (0)

    const int nchunks = kdim / 32;
    G_ISSUE(0, 0);
    G_ISSUE(1, 32);
    for (int ch = 0; ch < nchunks; ch++) {
        const int s = ch % 3;
        __syncthreads();                       // stage (ch+2)%3 fully consumed
        if (ch + 2 < nchunks)      { G_ISSUE((ch + 2) % 3, (ch + 2) * 32); cpa_wait2(); }
        else if (ch + 1 < nchunks) { cpa_wait1(); }
        else                       { cpa_wait0(); }
        __syncthreads();

        const uint32_t stb = sb + s * G_STG;
        const uint32_t aBH = stb + (wm * 32 + lr8 + ((g & 1) << 3)) * 80 + ((g >> 1) << 4);
        const uint32_t aBL = aBH + G_AL;
        const uint32_t bBH = stb + G_BH + (lr8 + ((g & 1) << 3)) * 272 + wn * 128 + ((g >> 1) << 4);
        const uint32_t bBL = bBH + (G_BL - G_BH);

#pragma unroll
        for (int ks = 0; ks < 2; ks++) {
            uint32_t ah[2][4], al[2][4];
#pragma unroll
            for (int ma = 0; ma < 2; ma++) {
                ldsm4(ah[ma], aBH + ma * 1280 + ks * 32);
                ldsm4(al[ma], aBL + ma * 1280 + ks * 32);
            }
#pragma unroll
            for (int np = 0; np < 4; np++) {
                uint32_t bh4[4], bl4[4];
                ldsm4t(bh4, bBH + ks * 4352 + np * 32);
                ldsm4t(bl4, bBL + ks * 4352 + np * 32);
#pragma unroll
                for (int ma = 0; ma < 2; ma++) {
                    mma_bf16(c[ma][np * 2],     ah[ma], bh4);
                    mma_bf16(c[ma][np * 2],     ah[ma], bl4);
                    mma_bf16(c[ma][np * 2],     al[ma], bh4);
                    mma_bf16(c[ma][np * 2 + 1], ah[ma], bh4 + 2);
                    mma_bf16(c[ma][np * 2 + 1], ah[ma], bl4 + 2);
                    mma_bf16(c[ma][np * 2 + 1], al[ma], bh4 + 2);
                }
            }
        }
    }
#undef G_ISSUE

#pragma unroll
    for (int ma = 0; ma < 2; ma++) {
#pragma unroll
        for (int na = 0; na < 8; na++) {
            int r   = wm * 32 + ma * 16 + lr;
            int col = wn * 64 + na * 8 + lc * 2;
            float b0 = bias[col], b1 = bias[col + 1];
            float v00 = c[ma][na][0] + b0, v01 = c[ma][na][1] + b1;
            float v10 = c[ma][na][2] + b0, v11 = c[ma][na][3] + b1;
            if (SPLIT_OUT) {
                int head = col >> 6, e = col & 63;
                __nv_bfloat16* ph = outH + head * outHS + (long)r * 64 + e;
                __nv_bfloat16* pl = outL + head * outHS + (long)r * 64 + e;
                uint32_t hh, ll;
                split_pack(v00, v01, hh, ll);
                *(uint32_t*)ph = hh; *(uint32_t*)pl = ll;
                split_pack(v10, v11, hh, ll);
                *(uint32_t*)(ph + 8 * 64) = hh; *(uint32_t*)(pl + 8 * 64) = ll;
            } else {
                *(float2*)(outF + (long)r * ldoF + col)       = make_float2(v00, v01);
                *(float2*)(outF + (long)(r + 8) * ldoF + col) = make_float2(v10, v11);
            }
        }
    }
}

__global__ __launch_bounds__(256, 2) void qkv_gemm(
    const float* __restrict__ bq, const float* __restrict__ bk, const float* __restrict__ bv)
{
    const int which = blockIdx.z;
    const int h0 = blockIdx.x * 2;
    const int b  = blockIdx.y >> 4;
    const int s0 = (blockIdx.y & 15) * 128;

    const __nv_bfloat16* Agh = g_xh[which] + ((long)b * S_ + s0) * D_;
    const __nv_bfloat16* Agl = g_xl[which] + ((long)b * S_ + s0) * D_;
    const __nv_bfloat16* Bgh = g_wh[which] + (long)h0 * D_ * HD_;
    const __nv_bfloat16* Bgl = g_wl[which] + (long)h0 * D_ * HD_;
    const float* bias = ((which == 0) ? bq : (which == 1) ? bk : bv) + h0 * HD_;

    long ob = ((long)(b * H_ + h0) * S_ + s0) * HD_;
    __nv_bfloat16* oh = ((which == 0) ? g_qh : (which == 1) ? g_kh : g_vh) + ob;
    __nv_bfloat16* ol = ((which == 0) ? g_ql : (which == 1) ? g_kl : g_vl) + ob;

    gemm_body<true>(Agh, Agl, D_, D_, Bgh, Bgl, (long)D_ * HD_, HD_,
                    bias, nullptr, 0, oh, ol, (long)S_ * HD_);
}

__global__ __launch_bounds__(256, 2) void outproj_gemm(
    const float* __restrict__ bo, float* __restrict__ out)
{
    const int n0 = blockIdx.x * 128;
    const long m0 = (long)blockIdx.y * 128;
    gemm_body<false>(g_zh + m0 * D_, g_zl + m0 * D_, D_, D_,
                     g_woh + n0, g_wol + n0, 64, D_,
                     bo + n0, out + m0 * D_ + n0, D_, nullptr, nullptr, 0);
}

// ---------------------------------------------------------------------------
// Flash attention: 128 q-rows/block, 256 thr = 8 warps, 64-key tiles,
// 3-stage cp.async pipeline. Q pre-staged into stage 2.
// ---------------------------------------------------------------------------
#define A_STG  36864
#define A_KL   9216
#define A_VH   18432
#define A_VL   27648
#define ATT_DSM (3 * A_STG)

__global__ __launch_bounds__(256, 2) void attn_kernel()
{
    extern __shared__ uint8_t dyn[];
    const uint32_t sb = smem_u32(dyn);

    const int t = threadIdx.x, lane = t & 31, w = t >> 5;
    const int lr = lane >> 2, lc = lane & 3;
    const int g = lane >> 3, lr8 = lane & 7;
    const int bh = blockIdx.y, b = bh >> 4, h = bh & 15;
    const int q0 = blockIdx.x * 128;

    const __nv_bfloat16* qgh = g_qh + ((long)bh * S_ + q0) * HD_;
    const __nv_bfloat16* qgl = g_ql + ((long)bh * S_ + q0) * HD_;
    const __nv_bfloat16* khb = g_kh + (long)bh * S_ * HD_;
    const __nv_bfloat16* klb = g_kl + (long)bh * S_ * HD_;
    const __nv_bfloat16* vhb = g_vh + (long)bh * S_ * HD_;
    const __nv_bfloat16* vlb = g_vl + (long)bh * S_ * HD_;
    const float SC = 0.125f * 1.44269504088896340736f;

    // ---- stage Q [128 rows, hi/lo] into stage-2 buffer, extract frags ----
#pragma unroll
    for (int j = 0; j < 4; j++) {
        int idx = t + j * 256, r = idx >> 3, cc = idx & 7;
        uint32_t dh = (r < 64) ? (sb + 2 * A_STG + r * 144)
                               : (sb + 2 * A_STG + A_VH + (r - 64) * 144);
        cpa16(dh + cc * 16,        qgh + (long)r * HD_ + cc * 8);
        cpa16(dh + A_KL + cc * 16, qgl + (long)r * HD_ + cc * 8);
    }
    cpa_commit();
    cpa_wait0();
    __syncthreads();

    uint32_t qh[4][4], ql[4][4];
    {
        uint32_t area = (w < 4) ? 0u : (uint32_t)A_VH;
        uint32_t qBH = sb + 2 * A_STG + area + ((w & 3) * 16 + lr8 + ((g & 1) << 3)) * 144 + ((g >> 1) << 4);
        uint32_t qBL = qBH + A_KL;
#pragma unroll
        for (int ks = 0; ks < 4; ks++) {
            ldsm4(qh[ks], qBH + ks * 32);
            ldsm4(ql[ks], qBL + ks * 32);
        }
    }
    __syncthreads();   // Q fully extracted before stage-2 reused (chunk 2)

#define KV_ISSUE(stg, k0) do { \
        uint32_t base_ = sb + (stg) * A_STG; \
        _Pragma("unroll") \
        for (int j = 0; j < 2; j++) { \
            int idx = t + j * 256, r = idx >> 3, cc = idx & 7; \
            long go = (long)((k0) + r) * HD_ + cc * 8; \
            cpa16(base_ + r * 144 + cc * 16,        khb + go); \
            cpa16(base_ + A_KL + r * 144 + cc * 16, klb + go); \
            cpa16(base_ + A_VH + r * 144 + cc * 16, vhb + go); \
            cpa16(base_ + A_VL + r * 144 + cc * 16, vlb + go); \
        } \
        cpa_commit(); \
    } while (0)

    float o[8][4];
#pragma unroll
    for (int i = 0; i < 8; i++)
#pragma unroll
        for (int j = 0; j < 4; j++) o[i][j] = 0.f;
    float lacc[2] = {0.f, 0.f};

    const int NT = S_ / 64;
    KV_ISSUE(0, 0);
    KV_ISSUE(1, 64);

    for (int kt = 0; kt < NT; kt++) {
        const int s = kt % 3;
        const int k0 = kt * 64;

        __syncthreads();                     // stage (kt+2)%3 fully consumed
        if (kt + 2 < NT)      { KV_ISSUE((kt + 2) % 3, k0 + 128); cpa_wait2(); }
        else if (kt + 1 < NT) { cpa_wait1(); }
        else                  { cpa_wait0(); }
        __syncthreads();

        uint32_t mw[2][2];
#pragma unroll
        for (int i = 0; i < 2; i++) {
            int q = q0 + w * 16 + lr + i * 8;
            const unsigned* mp = g_mpk + ((long)b * S_ + q) * (S_ / 32) + (k0 >> 5);
            mw[i][0] = mp[0]; mw[i][1] = mp[1];
        }

        const uint32_t stb = sb + s * A_STG;
        const uint32_t kBH = stb + (lr8 + ((g >= 2) << 3)) * 144 + ((g & 1) << 4);
        const uint32_t kBL = kBH + A_KL;
        const uint32_t vBH = stb + A_VH + (lr8 + ((g & 1) << 3)) * 144 + ((g >> 1) << 4);
        const uint32_t vBL = vBH + (A_VL - A_VH);

        float s_[8][4];
#pragma unroll
        for (int i = 0; i < 8; i++)
#pragma unroll
            for (int j = 0; j < 4; j++) s_[i][j] = 0.f;
#pragma unroll
        for (int ks = 0; ks < 4; ks++) {
#pragma unroll
            for (int np = 0; np < 4; np++) {
                uint32_t kb[4], kl4[4];
                ldsm4(kb,  kBH + np * 2304 + ks * 32);
                ldsm4(kl4, kBL + np * 2304 + ks * 32);
                mma_bf16(s_[np * 2],     qh[ks], kb);
                mma_bf16(s_[np * 2],     qh[ks], kl4);
                mma_bf16(s_[np * 2],     ql[ks], kb);
                mma_bf16(s_[np * 2 + 1], qh[ks], kb + 2);
                mma_bf16(s_[np * 2 + 1], qh[ks], kl4 + 2);
                mma_bf16(s_[np * 2 + 1], ql[ks], kb + 2);
            }
        }

#pragma unroll
        for (int i = 0; i < 2; i++) {
#pragma unroll
            for (int na = 0; na < 8; na++) {
                uint32_t wbits = mw[i][na >> 2];
                int bit = (na & 3) * 8 + lc * 2;
                float v0 = ((wbits >> bit) & 1)       ? s_[na][i * 2] * SC     : 0.f;
                float v1 = ((wbits >> (bit + 1)) & 1) ? s_[na][i * 2 + 1] * SC : 0.f;
                float p0 = ex2(v0), p1 = ex2(v1);
                s_[na][i * 2] = p0; s_[na][i * 2 + 1] = p1;
                lacc[i] += p0 + p1;
            }
        }

        uint32_t pah[4][4], pal[4][4];
#pragma unroll
        for (int ks = 0; ks < 4; ks++) {
            split_pack(s_[2 * ks][0],     s_[2 * ks][1],     pah[ks][0], pal[ks][0]);
            split_pack(s_[2 * ks][2],     s_[2 * ks][3],     pah[ks][1], pal[ks][1]);
            split_pack(s_[2 * ks + 1][0], s_[2 * ks + 1][1], pah[ks][2], pal[ks][2]);
            split_pack(s_[2 * ks + 1][2], s_[2 * ks + 1][3], pah[ks][3], pal[ks][3]);
        }

#pragma unroll
        for (int ks = 0; ks < 4; ks++) {
#pragma unroll
            for (int np = 0; np < 4; np++) {
                uint32_t vb[4], vl4[4];
                ldsm4t(vb,  vBH + ks * 2304 + np * 32);
                ldsm4t(vl4, vBL + ks * 2304 + np * 32);
                mma_bf16(o[np * 2],     pah[ks], vb);
                mma_bf16(o[np * 2],     pah[ks], vl4);
                mma_bf16(o[np * 2],     pal[ks], vb);
                mma_bf16(o[np * 2 + 1], pah[ks], vb + 2);
                mma_bf16(o[np * 2 + 1], pah[ks], vl4 + 2);
                mma_bf16(o[np * 2 + 1], pal[ks], vb + 2);
            }
        }
    }
#undef KV_ISSUE

#pragma unroll
    for (int i = 0; i < 2; i++) {
        lacc[i] += __shfl_xor_sync(0xffffffffu, lacc[i], 1);
        lacc[i] += __shfl_xor_sync(0xffffffffu, lacc[i], 2);
        float inv = 1.f / lacc[i];
        int q = q0 + w * 16 + lr + i * 8;
        __nv_bfloat16* zh = g_zh + ((long)b * S_ + q) * D_ + h * HD_;
        __nv_bfloat16* zl = g_zl + ((long)b * S_ + q) * D_ + h * HD_;
#pragma unroll
        for (int na = 0; na < 8; na++) {
            uint32_t hh, ll;
            split_pack(o[na][i * 2] * inv, o[na][i * 2 + 1] * inv, hh, ll);
            *(uint32_t*)(zh + na * 8 + lc * 2) = hh;
            *(uint32_t*)(zl + na * 8 + lc * 2) = ll;
        }
    }
}

// ---------------------------------------------------------------------------
extern "C" void kernel_launch(void* const* d_in, const int* in_sizes, int n_in,
                              void* d_out, int out_size)
{
    const float* xv   = (const float*)d_in[0];
    const float* xk   = (const float*)d_in[1];
    const float* xq   = (const float*)d_in[2];
    const int*   mask = (const int*)  d_in[3];
    const float* Wq   = (const float*)d_in[4];
    const float* bq   = (const float*)d_in[5];
    const float* Wk   = (const float*)d_in[6];
    const float* bk   = (const float*)d_in[7];
    const float* Wv   = (const float*)d_in[8];
    const float* bv   = (const float*)d_in[9];
    const float* Wo   = (const float*)d_in[10];
    const float* bo   = (const float*)d_in[11];
    float* out = (float*)d_out;

    cudaFuncSetAttribute(qkv_gemm,     cudaFuncAttributeMaxDynamicSharedMemorySize, GEMM_DSM);
    cudaFuncSetAttribute(outproj_gemm, cudaFuncAttributeMaxDynamicSharedMemorySize, GEMM_DSM);
    cudaFuncSetAttribute(attn_kernel,  cudaFuncAttributeMaxDynamicSharedMemorySize, ATT_DSM);

    split_x_kernel<<<3 * 8192, 256>>>(xq, xk, xv);
    split_w_kernel<<<4 * 1024, 256>>>(Wq, Wk, Wv, Wo);
    pack_mask_kernel<<<(B_ * S_ * (S_ / 32) + 255) / 256, 256>>>(mask);
    qkv_gemm<<<dim3(H_ / 2, 64, 3), 256, GEMM_DSM>>>(bq, bk, bv);
    attn_kernel<<<dim3(S_ / 128, B_ * H_), 256, ATT_DSM>>>();
    outproj_gemm<<<dim3(D_ / 128, (B_ * S_) / 128), 256, GEMM_DSM>>>(bo, out);
}

// round 13
// speedup vs baseline: 1.3649x; 1.3649x over previous
#include <cuda_runtime.h>
#include <cuda_fp16.h>
#include <cstdint>

#define B_  4
#define S_  2048
#define D_  1024
#define H_  16
#define HD_ 64

// ---------------------------------------------------------------------------
// Static scratch (fp16; hi/lo split only where operand is mma B-side)
// ---------------------------------------------------------------------------
__device__ __align__(16) __half g_xh[3][B_ * S_ * D_];                    // A-side: hi only
__device__ __align__(16) __half g_wh[3][H_ * D_ * HD_], g_wl[3][H_ * D_ * HD_];
__device__ __align__(16) __half g_woh[D_ * D_], g_wol[D_ * D_];
__device__ __align__(16) __half g_qh[B_*H_*S_*HD_];                       // Q: hi only (A-side)
__device__ __align__(16) __half g_kh[B_*H_*S_*HD_], g_kl[B_*H_*S_*HD_];
__device__ __align__(16) __half g_vh[B_*H_*S_*HD_], g_vl[B_*H_*S_*HD_];
__device__ __align__(16) __half g_zh[B_ * S_ * D_];                       // z: hi only (A-side)
__device__ unsigned g_mpk[B_ * S_ * (S_ / 32)];

// ---------------------------------------------------------------------------
// Helpers
// ---------------------------------------------------------------------------
__device__ __forceinline__ uint32_t pack2h(float x, float y) {
    __half2 t = __floats2half2_rn(x, y);
    return *reinterpret_cast<uint32_t*>(&t);
}
__device__ __forceinline__ void split_pack_h(float x, float y, uint32_t& hi, uint32_t& lo) {
    __half ax = __float2half_rn(x), ay = __float2half_rn(y);
    __half2 hv = __halves2half2(ax, ay);
    hi = *reinterpret_cast<uint32_t*>(&hv);
    __half lx = __float2half_rn(x - __half2float(ax));
    __half ly = __float2half_rn(y - __half2float(ay));
    __half2 lv = __halves2half2(lx, ly);
    lo = *reinterpret_cast<uint32_t*>(&lv);
}
__device__ __forceinline__ float ex2(float x) {
    float y; asm("ex2.approx.f32 %0, %1;" : "=f"(y) : "f"(x)); return y;
}
__device__ __forceinline__ uint32_t smem_u32(const void* p) {
    return (uint32_t)__cvta_generic_to_shared(p);
}
__device__ __forceinline__ void ldsm4(uint32_t r[4], uint32_t a) {
    asm volatile("ldmatrix.sync.aligned.m8n8.x4.shared.b16 {%0,%1,%2,%3}, [%4];"
                 : "=r"(r[0]), "=r"(r[1]), "=r"(r[2]), "=r"(r[3]) : "r"(a));
}
__device__ __forceinline__ void ldsm4t(uint32_t r[4], uint32_t a) {
    asm volatile("ldmatrix.sync.aligned.m8n8.x4.trans.shared.b16 {%0,%1,%2,%3}, [%4];"
                 : "=r"(r[0]), "=r"(r[1]), "=r"(r[2]), "=r"(r[3]) : "r"(a));
}
__device__ __forceinline__ void mma_f16(float c[4], const uint32_t a[4], const uint32_t b[2]) {
    asm volatile(
        "mma.sync.aligned.m16n8k16.row.col.f32.f16.f16.f32 "
        "{%0,%1,%2,%3}, {%4,%5,%6,%7}, {%8,%9}, {%0,%1,%2,%3};\n"
        : "+f"(c[0]), "+f"(c[1]), "+f"(c[2]), "+f"(c[3])
        : "r"(a[0]), "r"(a[1]), "r"(a[2]), "r"(a[3]), "r"(b[0]), "r"(b[1]));
}
__device__ __forceinline__ void cpa16(uint32_t saddr, const void* g) {
    asm volatile("cp.async.cg.shared.global [%0], [%1], 16;" :: "r"(saddr), "l"(g) : "memory");
}
__device__ __forceinline__ void cpa_commit() { asm volatile("cp.async.commit_group;" ::: "memory"); }
__device__ __forceinline__ void cpa_wait0()  { asm volatile("cp.async.wait_group 0;" ::: "memory"); }
__device__ __forceinline__ void cpa_wait1()  { asm volatile("cp.async.wait_group 1;" ::: "memory"); }

// ---------------------------------------------------------------------------
// Split kernels
// ---------------------------------------------------------------------------
__global__ void split_x_kernel(const float* __restrict__ xq, const float* __restrict__ xk,
                               const float* __restrict__ xv)
{
    const int which = blockIdx.x >> 13;
    const int i = (blockIdx.x & 8191) * 256 + threadIdx.x;
    const float* in = (which == 0) ? xq : (which == 1) ? xk : xv;
    float4 v = ((const float4*)in)[i];
    ((uint2*)g_xh[which])[i] = make_uint2(pack2h(v.x, v.y), pack2h(v.z, v.w));
}

__global__ void split_w_kernel(const float* __restrict__ Wq, const float* __restrict__ Wk,
                               const float* __restrict__ Wv, const float* __restrict__ Wo)
{
    const int dst = blockIdx.x >> 10;
    const int i = (blockIdx.x & 1023) * 256 + threadIdx.x;
    const float* in = (dst == 0) ? Wq : (dst == 1) ? Wk : (dst == 2) ? Wv : Wo;
    __half* hi = (dst < 3) ? g_wh[dst] : g_woh;
    __half* lo = (dst < 3) ? g_wl[dst] : g_wol;
    float4 v = ((const float4*)in)[i];
    uint32_t h0, l0, h1, l1;
    split_pack_h(v.x, v.y, h0, l0);
    split_pack_h(v.z, v.w, h1, l1);
    ((uint2*)hi)[i] = make_uint2(h0, h1);
    ((uint2*)lo)[i] = make_uint2(l0, l1);
}

__global__ void pack_mask_kernel(const int* __restrict__ mask)
{
    int i = blockIdx.x * 256 + threadIdx.x;
    if (i >= B_ * S_ * (S_ / 32)) return;
    const int4* mp = (const int4*)(mask + (long)i * 32);
    unsigned w = 0;
#pragma unroll
    for (int j = 0; j < 8; j++) {
        int4 m = mp[j];
        w |= (unsigned)(m.x != 0) << (j * 4 + 0);
        w |= (unsigned)(m.y != 0) << (j * 4 + 1);
        w |= (unsigned)(m.z != 0) << (j * 4 + 2);
        w |= (unsigned)(m.w != 0) << (j * 4 + 3);
    }
    g_mpk[i] = w;
}

// ---------------------------------------------------------------------------
// GEMM: 128(m) x 128(n) x kdim, k-chunks of 32, 2-stage cp.async pipeline.
// fp16 2-term: C += Ah*Bh + Ah*Bl   (A hi-only)
// Stage (27648 B): Ah[128x80] Bh[32x272] Bl[32x272]
// ---------------------------------------------------------------------------
#define G_STG   27648
#define G_BH    10240
#define G_BL    18944
#define GEMM_DSM (2 * G_STG)

template<bool SPLIT_OUT>
__device__ __forceinline__ void gemm_body(
    const __half* __restrict__ Agh, int lda, int kdim,
    const __half* __restrict__ Bgh, const __half* __restrict__ Bgl,
    long bHS, int ldb,
    const float* __restrict__ bias,
    float* __restrict__ outF, int ldoF,
    __half* __restrict__ outH, __half* __restrict__ outL, long outHS)
{
    extern __shared__ uint8_t dyn[];
    const uint32_t sb = smem_u32(dyn);

    const int t = threadIdx.x, lane = t & 31, warp = t >> 5;
    const int wm = warp >> 1, wn = warp & 1;
    const int lr = lane >> 2, lc = lane & 3;
    const int g = lane >> 3, lr8 = lane & 7;

    float c[2][8][4];
#pragma unroll
    for (int i = 0; i < 2; i++)
#pragma unroll
        for (int j = 0; j < 8; j++)
#pragma unroll
            for (int k = 0; k < 4; k++) c[i][j][k] = 0.f;

#define G_ISSUE(stg, k0) do { \
        uint32_t base_ = sb + (stg) * G_STG; \
        _Pragma("unroll") \
        for (int j = 0; j < 2; j++) { \
            int idx = t + j * 256, r = idx >> 2, cc = idx & 3; \
            cpa16(base_ + r * 80 + cc * 16, Agh + (long)r * lda + (k0) + cc * 8); \
        } \
        _Pragma("unroll") \
        for (int j = 0; j < 2; j++) { \
            int idx = t + j * 256, r = idx >> 4, n16 = idx & 15; \
            long src = (long)(n16 >> 3) * bHS + (long)((k0) + r) * ldb + (n16 & 7) * 8; \
            cpa16(base_ + G_BH + r * 272 + n16 * 16, Bgh + src); \
            cpa16(base_ + G_BL + r * 272 + n16 * 16, Bgl + src); \
        } \
        cpa_commit(); \
    } while (0)

    G_ISSUE(0, 0);
    const int nchunks = kdim / 32;
    for (int ch = 0; ch < nchunks; ch++) {
        const int s = ch & 1;
        __syncthreads();
        if (ch + 1 < nchunks) { G_ISSUE(1 - s, (ch + 1) * 32); cpa_wait1(); }
        else                  { cpa_wait0(); }
        __syncthreads();

        const uint32_t stb = sb + s * G_STG;
        const uint32_t aBH = stb + (wm * 32 + lr8 + ((g & 1) << 3)) * 80 + ((g >> 1) << 4);
        const uint32_t bBH = stb + G_BH + (lr8 + ((g & 1) << 3)) * 272 + wn * 128 + ((g >> 1) << 4);
        const uint32_t bBL = bBH + (G_BL - G_BH);

#pragma unroll
        for (int ks = 0; ks < 2; ks++) {
            uint32_t ah[2][4];
#pragma unroll
            for (int ma = 0; ma < 2; ma++)
                ldsm4(ah[ma], aBH + ma * 1280 + ks * 32);
#pragma unroll
            for (int np = 0; np < 4; np++) {
                uint32_t bh4[4], bl4[4];
                ldsm4t(bh4, bBH + ks * 4352 + np * 32);
                ldsm4t(bl4, bBL + ks * 4352 + np * 32);
#pragma unroll
                for (int ma = 0; ma < 2; ma++) {
                    mma_f16(c[ma][np * 2],     ah[ma], bh4);
                    mma_f16(c[ma][np * 2 + 1], ah[ma], bh4 + 2);
                    mma_f16(c[ma][np * 2],     ah[ma], bl4);
                    mma_f16(c[ma][np * 2 + 1], ah[ma], bl4 + 2);
                }
            }
        }
    }
#undef G_ISSUE

#pragma unroll
    for (int ma = 0; ma < 2; ma++) {
#pragma unroll
        for (int na = 0; na < 8; na++) {
            int r   = wm * 32 + ma * 16 + lr;
            int col = wn * 64 + na * 8 + lc * 2;
            float b0 = bias[col], b1 = bias[col + 1];
            float v00 = c[ma][na][0] + b0, v01 = c[ma][na][1] + b1;
            float v10 = c[ma][na][2] + b0, v11 = c[ma][na][3] + b1;
            if (SPLIT_OUT) {
                int head = col >> 6, e = col & 63;
                __half* ph = outH + head * outHS + (long)r * 64 + e;
                __half* pl = outL + head * outHS + (long)r * 64 + e;
                uint32_t hh, ll;
                split_pack_h(v00, v01, hh, ll);
                *(uint32_t*)ph = hh; *(uint32_t*)pl = ll;
                split_pack_h(v10, v11, hh, ll);
                *(uint32_t*)(ph + 8 * 64) = hh; *(uint32_t*)(pl + 8 * 64) = ll;
            } else {
                *(float2*)(outF + (long)r * ldoF + col)       = make_float2(v00, v01);
                *(float2*)(outF + (long)(r + 8) * ldoF + col) = make_float2(v10, v11);
            }
        }
    }
}

// q head outputs: hi target (attention reads hi only); k/v need hi+lo.
__device__ __half g_qlo_dummy[B_*H_*S_*HD_];   // discard target for q-lo

__global__ __launch_bounds__(256, 2) void qkv_gemm(
    const float* __restrict__ bq, const float* __restrict__ bk, const float* __restrict__ bv)
{
    const int which = blockIdx.z;
    const int h0 = blockIdx.x * 2;
    const int b  = blockIdx.y >> 4;
    const int s0 = (blockIdx.y & 15) * 128;

    const __half* Agh = g_xh[which] + ((long)b * S_ + s0) * D_;
    const __half* Bgh = g_wh[which] + (long)h0 * D_ * HD_;
    const __half* Bgl = g_wl[which] + (long)h0 * D_ * HD_;
    const float* bias = ((which == 0) ? bq : (which == 1) ? bk : bv) + h0 * HD_;

    long ob = ((long)(b * H_ + h0) * S_ + s0) * HD_;
    __half* oh = ((which == 0) ? g_qh : (which == 1) ? g_kh : g_vh) + ob;
    __half* ol = ((which == 0) ? g_qlo_dummy : (which == 1) ? g_kl : g_vl) + ob;

    gemm_body<true>(Agh, D_, D_, Bgh, Bgl, (long)D_ * HD_, HD_,
                    bias, nullptr, 0, oh, ol, (long)S_ * HD_);
}

__global__ __launch_bounds__(256, 2) void outproj_gemm(
    const float* __restrict__ bo, float* __restrict__ out)
{
    const int n0 = blockIdx.x * 128;
    const long m0 = (long)blockIdx.y * 128;
    gemm_body<false>(g_zh + m0 * D_, D_, D_,
                     g_woh + n0, g_wol + n0, 64, D_,
                     bo + n0, out + m0 * D_ + n0, D_, nullptr, nullptr, 0);
}

// ---------------------------------------------------------------------------
// Flash attention: 128 q-rows/block, 256 thr = 8 warps, 64-key tiles,
// 2-stage cp.async. fp16 2-term: S += Qh*(Kh+Kl); O += Pfp16*(Vh+Vl).
// Stage (36864 B): Kh Kl Vh Vl (9216 each). Q hi-only pre-staged in stage 1.
// ---------------------------------------------------------------------------
#define A_STG  36864
#define A_KL   9216
#define A_VH   18432
#define A_VL   27648
#define ATT_DSM (2 * A_STG)

__global__ __launch_bounds__(256, 2) void attn_kernel()
{
    extern __shared__ uint8_t dyn[];
    const uint32_t sb = smem_u32(dyn);

    const int t = threadIdx.x, lane = t & 31, w = t >> 5;
    const int lr = lane >> 2, lc = lane & 3;
    const int g = lane >> 3, lr8 = lane & 7;
    const int bh = blockIdx.y, b = bh >> 4, h = bh & 15;
    const int q0 = blockIdx.x * 128;

    const __half* qgh = g_qh + ((long)bh * S_ + q0) * HD_;
    const __half* khb = g_kh + (long)bh * S_ * HD_;
    const __half* klb = g_kl + (long)bh * S_ * HD_;
    const __half* vhb = g_vh + (long)bh * S_ * HD_;
    const __half* vlb = g_vl + (long)bh * S_ * HD_;
    const float SC = 0.125f * 1.44269504088896340736f;

    // ---- stage Q hi [128 rows] into stage-1 Kh/Vh areas ----
#pragma unroll
    for (int j = 0; j < 4; j++) {
        int idx = t + j * 256, r = idx >> 3, cc = idx & 7;
        uint32_t dh = (r < 64) ? (sb + A_STG + r * 144)
                               : (sb + A_STG + A_VH + (r - 64) * 144);
        cpa16(dh + cc * 16, qgh + (long)r * HD_ + cc * 8);
    }
    cpa_commit();
    cpa_wait0();
    __syncthreads();

    uint32_t qh[4][4];
    {
        uint32_t area = (w < 4) ? 0u : (uint32_t)A_VH;
        uint32_t qBH = sb + A_STG + area + ((w & 3) * 16 + lr8 + ((g & 1) << 3)) * 144 + ((g >> 1) << 4);
#pragma unroll
        for (int ks = 0; ks < 4; ks++)
            ldsm4(qh[ks], qBH + ks * 32);
    }
    __syncthreads();

#define KV_ISSUE(stg, k0) do { \
        uint32_t base_ = sb + (stg) * A_STG; \
        _Pragma("unroll") \
        for (int j = 0; j < 2; j++) { \
            int idx = t + j * 256, r = idx >> 3, cc = idx & 7; \
            long go = (long)((k0) + r) * HD_ + cc * 8; \
            cpa16(base_ + r * 144 + cc * 16,        khb + go); \
            cpa16(base_ + A_KL + r * 144 + cc * 16, klb + go); \
            cpa16(base_ + A_VH + r * 144 + cc * 16, vhb + go); \
            cpa16(base_ + A_VL + r * 144 + cc * 16, vlb + go); \
        } \
        cpa_commit(); \
    } while (0)

    float o[8][4];
#pragma unroll
    for (int i = 0; i < 8; i++)
#pragma unroll
        for (int j = 0; j < 4; j++) o[i][j] = 0.f;
    float lacc[2] = {0.f, 0.f};

    KV_ISSUE(0, 0);

    for (int kt = 0; kt < S_ / 64; kt++) {
        const int s = kt & 1;
        const int k0 = kt * 64;

        __syncthreads();
        if (kt + 1 < S_ / 64) { KV_ISSUE(1 - s, k0 + 64); cpa_wait1(); }
        else                  { cpa_wait0(); }
        __syncthreads();

        uint32_t mw[2][2];
#pragma unroll
        for (int i = 0; i < 2; i++) {
            int q = q0 + w * 16 + lr + i * 8;
            const unsigned* mp = g_mpk + ((long)b * S_ + q) * (S_ / 32) + (k0 >> 5);
            mw[i][0] = mp[0]; mw[i][1] = mp[1];
        }

        const uint32_t stb = sb + s * A_STG;
        const uint32_t kBH = stb + (lr8 + ((g >= 2) << 3)) * 144 + ((g & 1) << 4);
        const uint32_t kBL = kBH + A_KL;
        const uint32_t vBH = stb + A_VH + (lr8 + ((g & 1) << 3)) * 144 + ((g >> 1) << 4);
        const uint32_t vBL = vBH + (A_VL - A_VH);

        // ---- S = Qh (Kh + Kl)^T ----
        float s_[8][4];
#pragma unroll
        for (int i = 0; i < 8; i++)
#pragma unroll
            for (int j = 0; j < 4; j++) s_[i][j] = 0.f;
#pragma unroll
        for (int ks = 0; ks < 4; ks++) {
#pragma unroll
            for (int np = 0; np < 4; np++) {
                uint32_t kb[4], kl4[4];
                ldsm4(kb,  kBH + np * 2304 + ks * 32);
                ldsm4(kl4, kBL + np * 2304 + ks * 32);
                mma_f16(s_[np * 2],     qh[ks], kb);
                mma_f16(s_[np * 2 + 1], qh[ks], kb + 2);
                mma_f16(s_[np * 2],     qh[ks], kl4);
                mma_f16(s_[np * 2 + 1], qh[ks], kl4 + 2);
            }
        }

        // ---- mask + exp2 (fixed max 0) ----
#pragma unroll
        for (int i = 0; i < 2; i++) {
#pragma unroll
            for (int na = 0; na < 8; na++) {
                uint32_t wbits = mw[i][na >> 2];
                int bit = (na & 3) * 8 + lc * 2;
                float v0 = ((wbits >> bit) & 1)       ? s_[na][i * 2] * SC     : 0.f;
                float v1 = ((wbits >> (bit + 1)) & 1) ? s_[na][i * 2 + 1] * SC : 0.f;
                float p0 = ex2(v0), p1 = ex2(v1);
                s_[na][i * 2] = p0; s_[na][i * 2 + 1] = p1;
                lacc[i] += p0 + p1;
            }
        }

        // ---- P -> fp16 A-frags (single term, no split) ----
        uint32_t ph[4][4];
#pragma unroll
        for (int ks = 0; ks < 4; ks++) {
            ph[ks][0] = pack2h(s_[2 * ks][0],     s_[2 * ks][1]);
            ph[ks][1] = pack2h(s_[2 * ks][2],     s_[2 * ks][3]);
            ph[ks][2] = pack2h(s_[2 * ks + 1][0], s_[2 * ks + 1][1]);
            ph[ks][3] = pack2h(s_[2 * ks + 1][2], s_[2 * ks + 1][3]);
        }

        // ---- O += P (Vh + Vl) ----
#pragma unroll
        for (int ks = 0; ks < 4; ks++) {
#pragma unroll
            for (int np = 0; np < 4; np++) {
                uint32_t vb[4], vl4[4];
                ldsm4t(vb,  vBH + ks * 2304 + np * 32);
                ldsm4t(vl4, vBL + ks * 2304 + np * 32);
                mma_f16(o[np * 2],     ph[ks], vb);
                mma_f16(o[np * 2 + 1], ph[ks], vb + 2);
                mma_f16(o[np * 2],     ph[ks], vl4);
                mma_f16(o[np * 2 + 1], ph[ks], vl4 + 2);
            }
        }
    }
#undef KV_ISSUE

    // ---- epilogue: z hi-only ----
#pragma unroll
    for (int i = 0; i < 2; i++) {
        lacc[i] += __shfl_xor_sync(0xffffffffu, lacc[i], 1);
        lacc[i] += __shfl_xor_sync(0xffffffffu, lacc[i], 2);
        float inv = 1.f / lacc[i];
        int q = q0 + w * 16 + lr + i * 8;
        __half* zh = g_zh + ((long)b * S_ + q) * D_ + h * HD_;
#pragma unroll
        for (int na = 0; na < 8; na++) {
            *(uint32_t*)(zh + na * 8 + lc * 2) =
                pack2h(o[na][i * 2] * inv, o[na][i * 2 + 1] * inv);
        }
    }
}

// ---------------------------------------------------------------------------
extern "C" void kernel_launch(void* const* d_in, const int* in_sizes, int n_in,
                              void* d_out, int out_size)
{
    const float* xv   = (const float*)d_in[0];
    const float* xk   = (const float*)d_in[1];
    const float* xq   = (const float*)d_in[2];
    const int*   mask = (const int*)  d_in[3];
    const float* Wq   = (const float*)d_in[4];
    const float* bq   = (const float*)d_in[5];
    const float* Wk   = (const float*)d_in[6];
    const float* bk   = (const float*)d_in[7];
    const float* Wv   = (const float*)d_in[8];
    const float* bv   = (const float*)d_in[9];
    const float* Wo   = (const float*)d_in[10];
    const float* bo   = (const float*)d_in[11];
    float* out = (float*)d_out;

    cudaFuncSetAttribute(qkv_gemm,     cudaFuncAttributeMaxDynamicSharedMemorySize, GEMM_DSM);
    cudaFuncSetAttribute(outproj_gemm, cudaFuncAttributeMaxDynamicSharedMemorySize, GEMM_DSM);
    cudaFuncSetAttribute(attn_kernel,  cudaFuncAttributeMaxDynamicSharedMemorySize, ATT_DSM);

    split_x_kernel<<<3 * 8192, 256>>>(xq, xk, xv);
    split_w_kernel<<<4 * 1024, 256>>>(Wq, Wk, Wv, Wo);
    pack_mask_kernel<<<(B_ * S_ * (S_ / 32) + 255) / 256, 256>>>(mask);
    qkv_gemm<<<dim3(H_ / 2, 64, 3), 256, GEMM_DSM>>>(bq, bk, bv);
    attn_kernel<<<dim3(S_ / 128, B_ * H_), 256, ATT_DSM>>>();
    outproj_gemm<<<dim3(D_ / 128, (B_ * S_) / 128), 256, GEMM_DSM>>>(bo, out);
}

// round 14
// speedup vs baseline: 1.6874x; 1.2363x over previous
#include <cuda_runtime.h>
#include <cuda_fp16.h>
#include <cstdint>

#define B_  4
#define S_  2048
#define D_  1024
#define H_  16
#define HD_ 64

// ---------------------------------------------------------------------------
// Static scratch (fp16). Only W keeps a lo term; q/k/v/z are hi-only.
// ---------------------------------------------------------------------------
__device__ __align__(16) __half g_xh[3][B_ * S_ * D_];
__device__ __align__(16) __half g_wh[3][H_ * D_ * HD_], g_wl[3][H_ * D_ * HD_];
__device__ __align__(16) __half g_woh[D_ * D_], g_wol[D_ * D_];
__device__ __align__(16) __half g_qh[B_*H_*S_*HD_];
__device__ __align__(16) __half g_kh[B_*H_*S_*HD_];
__device__ __align__(16) __half g_vh[B_*H_*S_*HD_];
__device__ __align__(16) __half g_zh[B_ * S_ * D_];
__device__ unsigned g_mpk[B_ * S_ * (S_ / 32)];

// ---------------------------------------------------------------------------
// Helpers
// ---------------------------------------------------------------------------
__device__ __forceinline__ uint32_t pack2h(float x, float y) {
    __half2 t = __floats2half2_rn(x, y);
    return *reinterpret_cast<uint32_t*>(&t);
}
__device__ __forceinline__ void split_pack_h(float x, float y, uint32_t& hi, uint32_t& lo) {
    __half ax = __float2half_rn(x), ay = __float2half_rn(y);
    __half2 hv = __halves2half2(ax, ay);
    hi = *reinterpret_cast<uint32_t*>(&hv);
    __half lx = __float2half_rn(x - __half2float(ax));
    __half ly = __float2half_rn(y - __half2float(ay));
    __half2 lv = __halves2half2(lx, ly);
    lo = *reinterpret_cast<uint32_t*>(&lv);
}
__device__ __forceinline__ float ex2(float x) {
    float y; asm("ex2.approx.f32 %0, %1;" : "=f"(y) : "f"(x)); return y;
}
__device__ __forceinline__ uint32_t smem_u32(const void* p) {
    return (uint32_t)__cvta_generic_to_shared(p);
}
__device__ __forceinline__ void ldsm4(uint32_t r[4], uint32_t a) {
    asm volatile("ldmatrix.sync.aligned.m8n8.x4.shared.b16 {%0,%1,%2,%3}, [%4];"
                 : "=r"(r[0]), "=r"(r[1]), "=r"(r[2]), "=r"(r[3]) : "r"(a));
}
__device__ __forceinline__ void ldsm4t(uint32_t r[4], uint32_t a) {
    asm volatile("ldmatrix.sync.aligned.m8n8.x4.trans.shared.b16 {%0,%1,%2,%3}, [%4];"
                 : "=r"(r[0]), "=r"(r[1]), "=r"(r[2]), "=r"(r[3]) : "r"(a));
}
__device__ __forceinline__ void mma_f16(float c[4], const uint32_t a[4], const uint32_t b[2]) {
    asm volatile(
        "mma.sync.aligned.m16n8k16.row.col.f32.f16.f16.f32 "
        "{%0,%1,%2,%3}, {%4,%5,%6,%7}, {%8,%9}, {%0,%1,%2,%3};\n"
        : "+f"(c[0]), "+f"(c[1]), "+f"(c[2]), "+f"(c[3])
        : "r"(a[0]), "r"(a[1]), "r"(a[2]), "r"(a[3]), "r"(b[0]), "r"(b[1]));
}
__device__ __forceinline__ void cpa16(uint32_t saddr, const void* g) {
    asm volatile("cp.async.cg.shared.global [%0], [%1], 16;" :: "r"(saddr), "l"(g) : "memory");
}
__device__ __forceinline__ void cpa_commit() { asm volatile("cp.async.commit_group;" ::: "memory"); }
__device__ __forceinline__ void cpa_wait0()  { asm volatile("cp.async.wait_group 0;" ::: "memory"); }
__device__ __forceinline__ void cpa_wait1()  { asm volatile("cp.async.wait_group 1;" ::: "memory"); }

// ---------------------------------------------------------------------------
// Split kernels
// ---------------------------------------------------------------------------
__global__ void split_x_kernel(const float* __restrict__ xq, const float* __restrict__ xk,
                               const float* __restrict__ xv)
{
    const int which = blockIdx.x >> 13;
    const int i = (blockIdx.x & 8191) * 256 + threadIdx.x;
    const float* in = (which == 0) ? xq : (which == 1) ? xk : xv;
    float4 v = ((const float4*)in)[i];
    ((uint2*)g_xh[which])[i] = make_uint2(pack2h(v.x, v.y), pack2h(v.z, v.w));
}

__global__ void split_w_kernel(const float* __restrict__ Wq, const float* __restrict__ Wk,
                               const float* __restrict__ Wv, const float* __restrict__ Wo)
{
    const int dst = blockIdx.x >> 10;
    const int i = (blockIdx.x & 1023) * 256 + threadIdx.x;
    const float* in = (dst == 0) ? Wq : (dst == 1) ? Wk : (dst == 2) ? Wv : Wo;
    __half* hi = (dst < 3) ? g_wh[dst] : g_woh;
    __half* lo = (dst < 3) ? g_wl[dst] : g_wol;
    float4 v = ((const float4*)in)[i];
    uint32_t h0, l0, h1, l1;
    split_pack_h(v.x, v.y, h0, l0);
    split_pack_h(v.z, v.w, h1, l1);
    ((uint2*)hi)[i] = make_uint2(h0, h1);
    ((uint2*)lo)[i] = make_uint2(l0, l1);
}

__global__ void pack_mask_kernel(const int* __restrict__ mask)
{
    int i = blockIdx.x * 256 + threadIdx.x;
    if (i >= B_ * S_ * (S_ / 32)) return;
    const int4* mp = (const int4*)(mask + (long)i * 32);
    unsigned w = 0;
#pragma unroll
    for (int j = 0; j < 8; j++) {
        int4 m = mp[j];
        w |= (unsigned)(m.x != 0) << (j * 4 + 0);
        w |= (unsigned)(m.y != 0) << (j * 4 + 1);
        w |= (unsigned)(m.z != 0) << (j * 4 + 2);
        w |= (unsigned)(m.w != 0) << (j * 4 + 3);
    }
    g_mpk[i] = w;
}

// ---------------------------------------------------------------------------
// GEMM: 128(m) x 128(n) x kdim, k-chunks of 32, 2-stage cp.async pipeline.
// fp16 2-term: C += Ah*Bh + Ah*Bl.  SPLIT_OUT epilogue emits hi-only fp16.
// Stage (27648 B): Ah[128x80] Bh[32x272] Bl[32x272]
// ---------------------------------------------------------------------------
#define G_STG   27648
#define G_BH    10240
#define G_BL    18944
#define GEMM_DSM (2 * G_STG)

template<bool SPLIT_OUT>
__device__ __forceinline__ void gemm_body(
    const __half* __restrict__ Agh, int lda, int kdim,
    const __half* __restrict__ Bgh, const __half* __restrict__ Bgl,
    long bHS, int ldb,
    const float* __restrict__ bias,
    float* __restrict__ outF, int ldoF,
    __half* __restrict__ outH, long outHS)
{
    extern __shared__ uint8_t dyn[];
    const uint32_t sb = smem_u32(dyn);

    const int t = threadIdx.x, lane = t & 31, warp = t >> 5;
    const int wm = warp >> 1, wn = warp & 1;
    const int lr = lane >> 2, lc = lane & 3;
    const int g = lane >> 3, lr8 = lane & 7;

    float c[2][8][4];
#pragma unroll
    for (int i = 0; i < 2; i++)
#pragma unroll
        for (int j = 0; j < 8; j++)
#pragma unroll
            for (int k = 0; k < 4; k++) c[i][j][k] = 0.f;

#define G_ISSUE(stg, k0) do { \
        uint32_t base_ = sb + (stg) * G_STG; \
        _Pragma("unroll") \
        for (int j = 0; j < 2; j++) { \
            int idx = t + j * 256, r = idx >> 2, cc = idx & 3; \
            cpa16(base_ + r * 80 + cc * 16, Agh + (long)r * lda + (k0) + cc * 8); \
        } \
        _Pragma("unroll") \
        for (int j = 0; j < 2; j++) { \
            int idx = t + j * 256, r = idx >> 4, n16 = idx & 15; \
            long src = (long)(n16 >> 3) * bHS + (long)((k0) + r) * ldb + (n16 & 7) * 8; \
            cpa16(base_ + G_BH + r * 272 + n16 * 16, Bgh + src); \
            cpa16(base_ + G_BL + r * 272 + n16 * 16, Bgl + src); \
        } \
        cpa_commit(); \
    } while (0)

    G_ISSUE(0, 0);
    const int nchunks = kdim / 32;
    for (int ch = 0; ch < nchunks; ch++) {
        const int s = ch & 1;
        __syncthreads();
        if (ch + 1 < nchunks) { G_ISSUE(1 - s, (ch + 1) * 32); cpa_wait1(); }
        else                  { cpa_wait0(); }
        __syncthreads();

        const uint32_t stb = sb + s * G_STG;
        const uint32_t aBH = stb + (wm * 32 + lr8 + ((g & 1) << 3)) * 80 + ((g >> 1) << 4);
        const uint32_t bBH = stb + G_BH + (lr8 + ((g & 1) << 3)) * 272 + wn * 128 + ((g >> 1) << 4);
        const uint32_t bBL = bBH + (G_BL - G_BH);

#pragma unroll
        for (int ks = 0; ks < 2; ks++) {
            uint32_t ah[2][4];
#pragma unroll
            for (int ma = 0; ma < 2; ma++)
                ldsm4(ah[ma], aBH + ma * 1280 + ks * 32);
#pragma unroll
            for (int np = 0; np < 4; np++) {
                uint32_t bh4[4], bl4[4];
                ldsm4t(bh4, bBH + ks * 4352 + np * 32);
                ldsm4t(bl4, bBL + ks * 4352 + np * 32);
#pragma unroll
                for (int ma = 0; ma < 2; ma++) {
                    mma_f16(c[ma][np * 2],     ah[ma], bh4);
                    mma_f16(c[ma][np * 2 + 1], ah[ma], bh4 + 2);
                    mma_f16(c[ma][np * 2],     ah[ma], bl4);
                    mma_f16(c[ma][np * 2 + 1], ah[ma], bl4 + 2);
                }
            }
        }
    }
#undef G_ISSUE

#pragma unroll
    for (int ma = 0; ma < 2; ma++) {
#pragma unroll
        for (int na = 0; na < 8; na++) {
            int r   = wm * 32 + ma * 16 + lr;
            int col = wn * 64 + na * 8 + lc * 2;
            float b0 = bias[col], b1 = bias[col + 1];
            float v00 = c[ma][na][0] + b0, v01 = c[ma][na][1] + b1;
            float v10 = c[ma][na][2] + b0, v11 = c[ma][na][3] + b1;
            if (SPLIT_OUT) {
                int head = col >> 6, e = col & 63;
                __half* ph = outH + head * outHS + (long)r * 64 + e;
                *(uint32_t*)ph            = pack2h(v00, v01);
                *(uint32_t*)(ph + 8 * 64) = pack2h(v10, v11);
            } else {
                *(float2*)(outF + (long)r * ldoF + col)       = make_float2(v00, v01);
                *(float2*)(outF + (long)(r + 8) * ldoF + col) = make_float2(v10, v11);
            }
        }
    }
}

__global__ __launch_bounds__(256, 2) void qkv_gemm(
    const float* __restrict__ bq, const float* __restrict__ bk, const float* __restrict__ bv)
{
    const int which = blockIdx.z;
    const int h0 = blockIdx.x * 2;
    const int b  = blockIdx.y >> 4;
    const int s0 = (blockIdx.y & 15) * 128;

    const __half* Agh = g_xh[which] + ((long)b * S_ + s0) * D_;
    const __half* Bgh = g_wh[which] + (long)h0 * D_ * HD_;
    const __half* Bgl = g_wl[which] + (long)h0 * D_ * HD_;
    const float* bias = ((which == 0) ? bq : (which == 1) ? bk : bv) + h0 * HD_;

    long ob = ((long)(b * H_ + h0) * S_ + s0) * HD_;
    __half* oh = ((which == 0) ? g_qh : (which == 1) ? g_kh : g_vh) + ob;

    gemm_body<true>(Agh, D_, D_, Bgh, Bgl, (long)D_ * HD_, HD_,
                    bias, nullptr, 0, oh, (long)S_ * HD_);
}

__global__ __launch_bounds__(256, 2) void outproj_gemm(
    const float* __restrict__ bo, float* __restrict__ out)
{
    const int n0 = blockIdx.x * 128;
    const long m0 = (long)blockIdx.y * 128;
    gemm_body<false>(g_zh + m0 * D_, D_, D_,
                     g_woh + n0, g_wol + n0, 64, D_,
                     bo + n0, out + m0 * D_ + n0, D_, nullptr, 0);
}

// ---------------------------------------------------------------------------
// Flash attention: 128 q-rows/block, 256 thr = 8 warps, 64-key tiles,
// 2-stage cp.async. Pure fp16 single-term: S = Qh*Kh^T, O += P*Vh.
// Stage (18432 B): Kh[64x144] Vh[64x144]. Q pre-staged across stage 1.
// ---------------------------------------------------------------------------
#define A_STG  18432
#define A_VH   9216
#define ATT_DSM (2 * A_STG)

__global__ __launch_bounds__(256, 2) void attn_kernel()
{
    extern __shared__ uint8_t dyn[];
    const uint32_t sb = smem_u32(dyn);

    const int t = threadIdx.x, lane = t & 31, w = t >> 5;
    const int lr = lane >> 2, lc = lane & 3;
    const int g = lane >> 3, lr8 = lane & 7;
    const int bh = blockIdx.y, b = bh >> 4, h = bh & 15;
    const int q0 = blockIdx.x * 128;

    const __half* qgh = g_qh + ((long)bh * S_ + q0) * HD_;
    const __half* khb = g_kh + (long)bh * S_ * HD_;
    const __half* vhb = g_vh + (long)bh * S_ * HD_;
    const float SC = 0.125f * 1.44269504088896340736f;

    // ---- stage Q hi [128 rows] into stage-1 (rows 0-63 Kh area, 64-127 Vh) ----
#pragma unroll
    for (int j = 0; j < 4; j++) {
        int idx = t + j * 256, r = idx >> 3, cc = idx & 7;
        uint32_t dh = (r < 64) ? (sb + A_STG + r * 144)
                               : (sb + A_STG + A_VH + (r - 64) * 144);
        cpa16(dh + cc * 16, qgh + (long)r * HD_ + cc * 8);
    }
    cpa_commit();
    cpa_wait0();
    __syncthreads();

    uint32_t qh[4][4];
    {
        uint32_t area = (w < 4) ? 0u : (uint32_t)A_VH;
        uint32_t qBH = sb + A_STG + area + ((w & 3) * 16 + lr8 + ((g & 1) << 3)) * 144 + ((g >> 1) << 4);
#pragma unroll
        for (int ks = 0; ks < 4; ks++)
            ldsm4(qh[ks], qBH + ks * 32);
    }
    __syncthreads();

#define KV_ISSUE(stg, k0) do { \
        uint32_t base_ = sb + (stg) * A_STG; \
        _Pragma("unroll") \
        for (int j = 0; j < 2; j++) { \
            int idx = t + j * 256, r = idx >> 3, cc = idx & 7; \
            long go = (long)((k0) + r) * HD_ + cc * 8; \
            cpa16(base_ + r * 144 + cc * 16,        khb + go); \
            cpa16(base_ + A_VH + r * 144 + cc * 16, vhb + go); \
        } \
        cpa_commit(); \
    } while (0)

    float o[8][4];
#pragma unroll
    for (int i = 0; i < 8; i++)
#pragma unroll
        for (int j = 0; j < 4; j++) o[i][j] = 0.f;
    float lacc[2] = {0.f, 0.f};

    KV_ISSUE(0, 0);

    for (int kt = 0; kt < S_ / 64; kt++) {
        const int s = kt & 1;
        const int k0 = kt * 64;

        __syncthreads();
        if (kt + 1 < S_ / 64) { KV_ISSUE(1 - s, k0 + 64); cpa_wait1(); }
        else                  { cpa_wait0(); }
        __syncthreads();

        uint32_t mw[2][2];
#pragma unroll
        for (int i = 0; i < 2; i++) {
            int q = q0 + w * 16 + lr + i * 8;
            const unsigned* mp = g_mpk + ((long)b * S_ + q) * (S_ / 32) + (k0 >> 5);
            mw[i][0] = mp[0]; mw[i][1] = mp[1];
        }

        const uint32_t stb = sb + s * A_STG;
        const uint32_t kBH = stb + (lr8 + ((g >= 2) << 3)) * 144 + ((g & 1) << 4);
        const uint32_t vBH = stb + A_VH + (lr8 + ((g & 1) << 3)) * 144 + ((g >> 1) << 4);

        // ---- S = Qh Kh^T ----
        float s_[8][4];
#pragma unroll
        for (int i = 0; i < 8; i++)
#pragma unroll
            for (int j = 0; j < 4; j++) s_[i][j] = 0.f;
#pragma unroll
        for (int ks = 0; ks < 4; ks++) {
#pragma unroll
            for (int np = 0; np < 4; np++) {
                uint32_t kb[4];
                ldsm4(kb, kBH + np * 2304 + ks * 32);
                mma_f16(s_[np * 2],     qh[ks], kb);
                mma_f16(s_[np * 2 + 1], qh[ks], kb + 2);
            }
        }

        // ---- mask + exp2 (fixed max 0) ----
#pragma unroll
        for (int i = 0; i < 2; i++) {
#pragma unroll
            for (int na = 0; na < 8; na++) {
                uint32_t wbits = mw[i][na >> 2];
                int bit = (na & 3) * 8 + lc * 2;
                float v0 = ((wbits >> bit) & 1)       ? s_[na][i * 2] * SC     : 0.f;
                float v1 = ((wbits >> (bit + 1)) & 1) ? s_[na][i * 2 + 1] * SC : 0.f;
                float p0 = ex2(v0), p1 = ex2(v1);
                s_[na][i * 2] = p0; s_[na][i * 2 + 1] = p1;
                lacc[i] += p0 + p1;
            }
        }

        // ---- P -> fp16 A-frags ----
        uint32_t ph[4][4];
#pragma unroll
        for (int ks = 0; ks < 4; ks++) {
            ph[ks][0] = pack2h(s_[2 * ks][0],     s_[2 * ks][1]);
            ph[ks][1] = pack2h(s_[2 * ks][2],     s_[2 * ks][3]);
            ph[ks][2] = pack2h(s_[2 * ks + 1][0], s_[2 * ks + 1][1]);
            ph[ks][3] = pack2h(s_[2 * ks + 1][2], s_[2 * ks + 1][3]);
        }

        // ---- O += P Vh ----
#pragma unroll
        for (int ks = 0; ks < 4; ks++) {
#pragma unroll
            for (int np = 0; np < 4; np++) {
                uint32_t vb[4];
                ldsm4t(vb, vBH + ks * 2304 + np * 32);
                mma_f16(o[np * 2],     ph[ks], vb);
                mma_f16(o[np * 2 + 1], ph[ks], vb + 2);
            }
        }
    }
#undef KV_ISSUE

    // ---- epilogue: z hi-only ----
#pragma unroll
    for (int i = 0; i < 2; i++) {
        lacc[i] += __shfl_xor_sync(0xffffffffu, lacc[i], 1);
        lacc[i] += __shfl_xor_sync(0xffffffffu, lacc[i], 2);
        float inv = 1.f / lacc[i];
        int q = q0 + w * 16 + lr + i * 8;
        __half* zh = g_zh + ((long)b * S_ + q) * D_ + h * HD_;
#pragma unroll
        for (int na = 0; na < 8; na++) {
            *(uint32_t*)(zh + na * 8 + lc * 2) =
                pack2h(o[na][i * 2] * inv, o[na][i * 2 + 1] * inv);
        }
    }
}

// ---------------------------------------------------------------------------
extern "C" void kernel_launch(void* const* d_in, const int* in_sizes, int n_in,
                              void* d_out, int out_size)
{
    const float* xv   = (const float*)d_in[0];
    const float* xk   = (const float*)d_in[1];
    const float* xq   = (const float*)d_in[2];
    const int*   mask = (const int*)  d_in[3];
    const float* Wq   = (const float*)d_in[4];
    const float* bq   = (const float*)d_in[5];
    const float* Wk   = (const float*)d_in[6];
    const float* bk   = (const float*)d_in[7];
    const float* Wv   = (const float*)d_in[8];
    const float* bv   = (const float*)d_in[9];
    const float* Wo   = (const float*)d_in[10];
    const float* bo   = (const float*)d_in[11];
    float* out = (float*)d_out;

    cudaFuncSetAttribute(qkv_gemm,     cudaFuncAttributeMaxDynamicSharedMemorySize, GEMM_DSM);
    cudaFuncSetAttribute(outproj_gemm, cudaFuncAttributeMaxDynamicSharedMemorySize, GEMM_DSM);
    cudaFuncSetAttribute(attn_kernel,  cudaFuncAttributeMaxDynamicSharedMemorySize, ATT_DSM);

    split_x_kernel<<<3 * 8192, 256>>>(xq, xk, xv);
    split_w_kernel<<<4 * 1024, 256>>>(Wq, Wk, Wv, Wo);
    pack_mask_kernel<<<(B_ * S_ * (S_ / 32) + 255) / 256, 256>>>(mask);
    qkv_gemm<<<dim3(H_ / 2, 64, 3), 256, GEMM_DSM>>>(bq, bk, bv);
    attn_kernel<<<dim3(S_ / 128, B_ * H_), 256, ATT_DSM>>>();
    outproj_gemm<<<dim3(D_ / 128, (B_ * S_) / 128), 256, GEMM_DSM>>>(bo, out);
}

// round 16
// speedup vs baseline: 2.2058x; 1.3072x over previous
#include <cuda_runtime.h>
#include <cuda_fp16.h>
#include <cstdint>

#define B_  4
#define S_  2048
#define D_  1024
#define H_  16
#define HD_ 64

// ---------------------------------------------------------------------------
// Static scratch — pure fp16 everywhere, no hi/lo splits.
// ---------------------------------------------------------------------------
__device__ __align__(16) __half g_xh[3][B_ * S_ * D_];
__device__ __align__(16) __half g_wh[3][H_ * D_ * HD_];
__device__ __align__(16) __half g_woh[D_ * D_];
__device__ __align__(16) __half g_qh[B_*H_*S_*HD_];
__device__ __align__(16) __half g_kh[B_*H_*S_*HD_];
__device__ __align__(16) __half g_vh[B_*H_*S_*HD_];
__device__ __align__(16) __half g_zh[B_ * S_ * D_];
__device__ unsigned g_mpk[B_ * S_ * (S_ / 32)];

// ---------------------------------------------------------------------------
// Helpers
// ---------------------------------------------------------------------------
__device__ __forceinline__ uint32_t pack2h(float x, float y) {
    __half2 t = __floats2half2_rn(x, y);
    return *reinterpret_cast<uint32_t*>(&t);
}
__device__ __forceinline__ float ex2(float x) {
    float y; asm("ex2.approx.f32 %0, %1;" : "=f"(y) : "f"(x)); return y;
}
__device__ __forceinline__ uint32_t smem_u32(const void* p) {
    return (uint32_t)__cvta_generic_to_shared(p);
}
__device__ __forceinline__ void ldsm4(uint32_t r[4], uint32_t a) {
    asm volatile("ldmatrix.sync.aligned.m8n8.x4.shared.b16 {%0,%1,%2,%3}, [%4];"
                 : "=r"(r[0]), "=r"(r[1]), "=r"(r[2]), "=r"(r[3]) : "r"(a));
}
__device__ __forceinline__ void ldsm4t(uint32_t r[4], uint32_t a) {
    asm volatile("ldmatrix.sync.aligned.m8n8.x4.trans.shared.b16 {%0,%1,%2,%3}, [%4];"
                 : "=r"(r[0]), "=r"(r[1]), "=r"(r[2]), "=r"(r[3]) : "r"(a));
}
__device__ __forceinline__ void mma_f16(float c[4], const uint32_t a[4], const uint32_t b[2]) {
    asm volatile(
        "mma.sync.aligned.m16n8k16.row.col.f32.f16.f16.f32 "
        "{%0,%1,%2,%3}, {%4,%5,%6,%7}, {%8,%9}, {%0,%1,%2,%3};\n"
        : "+f"(c[0]), "+f"(c[1]), "+f"(c[2]), "+f"(c[3])
        : "r"(a[0]), "r"(a[1]), "r"(a[2]), "r"(a[3]), "r"(b[0]), "r"(b[1]));
}
__device__ __forceinline__ void cpa16(uint32_t saddr, const void* g) {
    asm volatile("cp.async.cg.shared.global [%0], [%1], 16;" :: "r"(saddr), "l"(g) : "memory");
}
__device__ __forceinline__ void cpa_commit() { asm volatile("cp.async.commit_group;" ::: "memory"); }
__device__ __forceinline__ void cpa_wait0()  { asm volatile("cp.async.wait_group 0;" ::: "memory"); }
__device__ __forceinline__ void cpa_wait1()  { asm volatile("cp.async.wait_group 1;" ::: "memory"); }

// ---------------------------------------------------------------------------
// Cast kernels (fp32 -> fp16)
// ---------------------------------------------------------------------------
__global__ void split_x_kernel(const float* __restrict__ xq, const float* __restrict__ xk,
                               const float* __restrict__ xv)
{
    const int which = blockIdx.x >> 13;
    const int i = (blockIdx.x & 8191) * 256 + threadIdx.x;
    const float* in = (which == 0) ? xq : (which == 1) ? xk : xv;
    float4 v = ((const float4*)in)[i];
    ((uint2*)g_xh[which])[i] = make_uint2(pack2h(v.x, v.y), pack2h(v.z, v.w));
}

__global__ void split_w_kernel(const float* __restrict__ Wq, const float* __restrict__ Wk,
                               const float* __restrict__ Wv, const float* __restrict__ Wo)
{
    const int dst = blockIdx.x >> 10;
    const int i = (blockIdx.x & 1023) * 256 + threadIdx.x;
    const float* in = (dst == 0) ? Wq : (dst == 1) ? Wk : (dst == 2) ? Wv : Wo;
    __half* hi = (dst < 3) ? g_wh[dst] : g_woh;
    float4 v = ((const float4*)in)[i];
    ((uint2*)hi)[i] = make_uint2(pack2h(v.x, v.y), pack2h(v.z, v.w));
}

__global__ void pack_mask_kernel(const int* __restrict__ mask)
{
    int i = blockIdx.x * 256 + threadIdx.x;
    if (i >= B_ * S_ * (S_ / 32)) return;
    const int4* mp = (const int4*)(mask + (long)i * 32);
    unsigned w = 0;
#pragma unroll
    for (int j = 0; j < 8; j++) {
        int4 m = mp[j];
        w |= (unsigned)(m.x != 0) << (j * 4 + 0);
        w |= (unsigned)(m.y != 0) << (j * 4 + 1);
        w |= (unsigned)(m.z != 0) << (j * 4 + 2);
        w |= (unsigned)(m.w != 0) << (j * 4 + 3);
    }
    g_mpk[i] = w;
}

// ---------------------------------------------------------------------------
// GEMM: 128(m) x 128(n) x kdim, k-chunks of 32, 2-stage cp.async pipeline.
// Pure fp16 single-term. Stage (18944 B): Ah[128x80] Bh[32x272]
// ---------------------------------------------------------------------------
#define G_STG   18944
#define G_BH    10240
#define GEMM_DSM (2 * G_STG)

template<bool SPLIT_OUT>
__device__ __forceinline__ void gemm_body(
    const __half* __restrict__ Agh, int lda, int kdim,
    const __half* __restrict__ Bgh, long bHS, int ldb,
    const float* __restrict__ bias,
    float* __restrict__ outF, int ldoF,
    __half* __restrict__ outH, long outHS)
{
    extern __shared__ uint8_t dyn[];
    const uint32_t sb = smem_u32(dyn);

    const int t = threadIdx.x, lane = t & 31, warp = t >> 5;
    const int wm = warp >> 1, wn = warp & 1;
    const int lr = lane >> 2, lc = lane & 3;
    const int g = lane >> 3, lr8 = lane & 7;

    float c[2][8][4];
#pragma unroll
    for (int i = 0; i < 2; i++)
#pragma unroll
        for (int j = 0; j < 8; j++)
#pragma unroll
            for (int k = 0; k < 4; k++) c[i][j][k] = 0.f;

#define G_ISSUE(stg, k0) do { \
        uint32_t base_ = sb + (stg) * G_STG; \
        _Pragma("unroll") \
        for (int j = 0; j < 2; j++) { \
            int idx = t + j * 256, r = idx >> 2, cc = idx & 3; \
            cpa16(base_ + r * 80 + cc * 16, Agh + (long)r * lda + (k0) + cc * 8); \
        } \
        _Pragma("unroll") \
        for (int j = 0; j < 2; j++) { \
            int idx = t + j * 256, r = idx >> 4, n16 = idx & 15; \
            long src = (long)(n16 >> 3) * bHS + (long)((k0) + r) * ldb + (n16 & 7) * 8; \
            cpa16(base_ + G_BH + r * 272 + n16 * 16, Bgh + src); \
        } \
        cpa_commit(); \
    } while (0)

    G_ISSUE(0, 0);
    const int nchunks = kdim / 32;
    for (int ch = 0; ch < nchunks; ch++) {
        const int s = ch & 1;
        __syncthreads();
        if (ch + 1 < nchunks) { G_ISSUE(1 - s, (ch + 1) * 32); cpa_wait1(); }
        else                  { cpa_wait0(); }
        __syncthreads();

        const uint32_t stb = sb + s * G_STG;
        const uint32_t aBH = stb + (wm * 32 + lr8 + ((g & 1) << 3)) * 80 + ((g >> 1) << 4);
        const uint32_t bBH = stb + G_BH + (lr8 + ((g & 1) << 3)) * 272 + wn * 128 + ((g >> 1) << 4);

#pragma unroll
        for (int ks = 0; ks < 2; ks++) {
            uint32_t ah[2][4];
#pragma unroll
            for (int ma = 0; ma < 2; ma++)
                ldsm4(ah[ma], aBH + ma * 1280 + ks * 32);
#pragma unroll
            for (int np = 0; np < 4; np++) {
                uint32_t bh4[4];
                ldsm4t(bh4, bBH + ks * 4352 + np * 32);
#pragma unroll
                for (int ma = 0; ma < 2; ma++) {
                    mma_f16(c[ma][np * 2],     ah[ma], bh4);
                    mma_f16(c[ma][np * 2 + 1], ah[ma], bh4 + 2);
                }
            }
        }
    }
#undef G_ISSUE

#pragma unroll
    for (int ma = 0; ma < 2; ma++) {
#pragma unroll
        for (int na = 0; na < 8; na++) {
            int r   = wm * 32 + ma * 16 + lr;
            int col = wn * 64 + na * 8 + lc * 2;
            float b0 = bias[col], b1 = bias[col + 1];
            float v00 = c[ma][na][0] + b0, v01 = c[ma][na][1] + b1;
            float v10 = c[ma][na][2] + b0, v11 = c[ma][na][3] + b1;
            if (SPLIT_OUT) {
                int head = col >> 6, e = col & 63;
                __half* ph = outH + head * outHS + (long)r * 64 + e;
                *(uint32_t*)ph            = pack2h(v00, v01);
                *(uint32_t*)(ph + 8 * 64) = pack2h(v10, v11);
            } else {
                *(float2*)(outF + (long)r * ldoF + col)       = make_float2(v00, v01);
                *(float2*)(outF + (long)(r + 8) * ldoF + col) = make_float2(v10, v11);
            }
        }
    }
}

__global__ __launch_bounds__(256, 2) void qkv_gemm(
    const float* __restrict__ bq, const float* __restrict__ bk, const float* __restrict__ bv)
{
    const int which = blockIdx.z;
    const int h0 = blockIdx.x * 2;
    const int b  = blockIdx.y >> 4;
    const int s0 = (blockIdx.y & 15) * 128;

    const __half* Agh = g_xh[which] + ((long)b * S_ + s0) * D_;
    const __half* Bgh = g_wh[which] + (long)h0 * D_ * HD_;
    const float* bias = ((which == 0) ? bq : (which == 1) ? bk : bv) + h0 * HD_;

    long ob = ((long)(b * H_ + h0) * S_ + s0) * HD_;
    __half* oh = ((which == 0) ? g_qh : (which == 1) ? g_kh : g_vh) + ob;

    gemm_body<true>(Agh, D_, D_, Bgh, (long)D_ * HD_, HD_,
                    bias, nullptr, 0, oh, (long)S_ * HD_);
}

__global__ __launch_bounds__(256, 2) void outproj_gemm(
    const float* __restrict__ bo, float* __restrict__ out)
{
    const int n0 = blockIdx.x * 128;
    const long m0 = (long)blockIdx.y * 128;
    gemm_body<false>(g_zh + m0 * D_, D_, D_,
                     g_woh + n0, 64, D_,
                     bo + n0, out + m0 * D_ + n0, D_, nullptr, 0);
}

// ---------------------------------------------------------------------------
// Flash attention (R14-proven): 128 q-rows/block, 256 thr = 8 warps,
// 64-key tiles, 2-stage cp.async, pure fp16 single-term.
// Stage (18432 B): Kh[64x144] Vh[64x144]. Q pre-staged across stage 1.
// ---------------------------------------------------------------------------
#define A_STG  18432
#define A_VH   9216
#define ATT_DSM (2 * A_STG)

__global__ __launch_bounds__(256, 2) void attn_kernel()
{
    extern __shared__ uint8_t dyn[];
    const uint32_t sb = smem_u32(dyn);

    const int t = threadIdx.x, lane = t & 31, w = t >> 5;
    const int lr = lane >> 2, lc = lane & 3;
    const int g = lane >> 3, lr8 = lane & 7;
    const int bh = blockIdx.y, b = bh >> 4, h = bh & 15;
    const int q0 = blockIdx.x * 128;

    const __half* qgh = g_qh + ((long)bh * S_ + q0) * HD_;
    const __half* khb = g_kh + (long)bh * S_ * HD_;
    const __half* vhb = g_vh + (long)bh * S_ * HD_;
    const float SC = 0.125f * 1.44269504088896340736f;

#pragma unroll
    for (int j = 0; j < 4; j++) {
        int idx = t + j * 256, r = idx >> 3, cc = idx & 7;
        uint32_t dh = (r < 64) ? (sb + A_STG + r * 144)
                               : (sb + A_STG + A_VH + (r - 64) * 144);
        cpa16(dh + cc * 16, qgh + (long)r * HD_ + cc * 8);
    }
    cpa_commit();
    cpa_wait0();
    __syncthreads();

    uint32_t qh[4][4];
    {
        uint32_t area = (w < 4) ? 0u : (uint32_t)A_VH;
        uint32_t qBH = sb + A_STG + area + ((w & 3) * 16 + lr8 + ((g & 1) << 3)) * 144 + ((g >> 1) << 4);
#pragma unroll
        for (int ks = 0; ks < 4; ks++)
            ldsm4(qh[ks], qBH + ks * 32);
    }
    __syncthreads();

#define KV_ISSUE(stg, k0) do { \
        uint32_t base_ = sb + (stg) * A_STG; \
        _Pragma("unroll") \
        for (int j = 0; j < 2; j++) { \
            int idx = t + j * 256, r = idx >> 3, cc = idx & 7; \
            long go = (long)((k0) + r) * HD_ + cc * 8; \
            cpa16(base_ + r * 144 + cc * 16,        khb + go); \
            cpa16(base_ + A_VH + r * 144 + cc * 16, vhb + go); \
        } \
        cpa_commit(); \
    } while (0)

    float o[8][4];
#pragma unroll
    for (int i = 0; i < 8; i++)
#pragma unroll
        for (int j = 0; j < 4; j++) o[i][j] = 0.f;
    float lacc[2] = {0.f, 0.f};

    KV_ISSUE(0, 0);

    for (int kt = 0; kt < S_ / 64; kt++) {
        const int s = kt & 1;
        const int k0 = kt * 64;

        __syncthreads();
        if (kt + 1 < S_ / 64) { KV_ISSUE(1 - s, k0 + 64); cpa_wait1(); }
        else                  { cpa_wait0(); }
        __syncthreads();

        uint32_t mw[2][2];
#pragma unroll
        for (int i = 0; i < 2; i++) {
            int q = q0 + w * 16 + lr + i * 8;
            const unsigned* mp = g_mpk + ((long)b * S_ + q) * (S_ / 32) + (k0 >> 5);
            mw[i][0] = mp[0]; mw[i][1] = mp[1];
        }

        const uint32_t stb = sb + s * A_STG;
        const uint32_t kBH = stb + (lr8 + ((g >= 2) << 3)) * 144 + ((g & 1) << 4);
        const uint32_t vBH = stb + A_VH + (lr8 + ((g & 1) << 3)) * 144 + ((g >> 1) << 4);

        float s_[8][4];
#pragma unroll
        for (int i = 0; i < 8; i++)
#pragma unroll
            for (int j = 0; j < 4; j++) s_[i][j] = 0.f;
#pragma unroll
        for (int ks = 0; ks < 4; ks++) {
#pragma unroll
            for (int np = 0; np < 4; np++) {
                uint32_t kb[4];
                ldsm4(kb, kBH + np * 2304 + ks * 32);
                mma_f16(s_[np * 2],     qh[ks], kb);
                mma_f16(s_[np * 2 + 1], qh[ks], kb + 2);
            }
        }

#pragma unroll
        for (int i = 0; i < 2; i++) {
#pragma unroll
            for (int na = 0; na < 8; na++) {
                uint32_t wbits = mw[i][na >> 2];
                int bit = (na & 3) * 8 + lc * 2;
                float v0 = ((wbits >> bit) & 1)       ? s_[na][i * 2] * SC     : 0.f;
                float v1 = ((wbits >> (bit + 1)) & 1) ? s_[na][i * 2 + 1] * SC : 0.f;
                float p0 = ex2(v0), p1 = ex2(v1);
                s_[na][i * 2] = p0; s_[na][i * 2 + 1] = p1;
                lacc[i] += p0 + p1;
            }
        }

        uint32_t ph[4][4];
#pragma unroll
        for (int ks = 0; ks < 4; ks++) {
            ph[ks][0] = pack2h(s_[2 * ks][0],     s_[2 * ks][1]);
            ph[ks][1] = pack2h(s_[2 * ks][2],     s_[2 * ks][3]);
            ph[ks][2] = pack2h(s_[2 * ks + 1][0], s_[2 * ks + 1][1]);
            ph[ks][3] = pack2h(s_[2 * ks + 1][2], s_[2 * ks + 1][3]);
        }

#pragma unroll
        for (int ks = 0; ks < 4; ks++) {
#pragma unroll
            for (int np = 0; np < 4; np++) {
                uint32_t vb[4];
                ldsm4t(vb, vBH + ks * 2304 + np * 32);
                mma_f16(o[np * 2],     ph[ks], vb);
                mma_f16(o[np * 2 + 1], ph[ks], vb + 2);
            }
        }
    }
#undef KV_ISSUE

#pragma unroll
    for (int i = 0; i < 2; i++) {
        lacc[i] += __shfl_xor_sync(0xffffffffu, lacc[i], 1);
        lacc[i] += __shfl_xor_sync(0xffffffffu, lacc[i], 2);
        float inv = 1.f / lacc[i];
        int q = q0 + w * 16 + lr + i * 8;
        __half* zh = g_zh + ((long)b * S_ + q) * D_ + h * HD_;
#pragma unroll
        for (int na = 0; na < 8; na++) {
            *(uint32_t*)(zh + na * 8 + lc * 2) =
                pack2h(o[na][i * 2] * inv, o[na][i * 2 + 1] * inv);
        }
    }
}

// ---------------------------------------------------------------------------
extern "C" void kernel_launch(void* const* d_in, const int* in_sizes, int n_in,
                              void* d_out, int out_size)
{
    const float* xv   = (const float*)d_in[0];
    const float* xk   = (const float*)d_in[1];
    const float* xq   = (const float*)d_in[2];
    const int*   mask = (const int*)  d_in[3];
    const float* Wq   = (const float*)d_in[4];
    const float* bq   = (const float*)d_in[5];
    const float* Wk   = (const float*)d_in[6];
    const float* bk   = (const float*)d_in[7];
    const float* Wv   = (const float*)d_in[8];
    const float* bv   = (const float*)d_in[9];
    const float* Wo   = (const float*)d_in[10];
    const float* bo   = (const float*)d_in[11];
    float* out = (float*)d_out;

    cudaFuncSetAttribute(qkv_gemm,     cudaFuncAttributeMaxDynamicSharedMemorySize, GEMM_DSM);
    cudaFuncSetAttribute(outproj_gemm, cudaFuncAttributeMaxDynamicSharedMemorySize, GEMM_DSM);
    cudaFuncSetAttribute(attn_kernel,  cudaFuncAttributeMaxDynamicSharedMemorySize, ATT_DSM);

    split_x_kernel<<<3 * 8192, 256>>>(xq, xk, xv);
    split_w_kernel<<<4 * 1024, 256>>>(Wq, Wk, Wv, Wo);
    pack_mask_kernel<<<(B_ * S_ * (S_ / 32) + 255) / 256, 256>>>(mask);
    qkv_gemm<<<dim3(H_ / 2, 64, 3), 256, GEMM_DSM>>>(bq, bk, bv);
    attn_kernel<<<dim3(S_ / 128, B_ * H_), 256, ATT_DSM>>>();
    outproj_gemm<<<dim3(D_ / 128, (B_ * S_) / 128), 256, GEMM_DSM>>>(bo, out);
}

// round 17
// speedup vs baseline: 2.3648x; 1.0721x over previous
#include <cuda_runtime.h>
#include <cuda_fp16.h>
#include <cstdint>

#define B_  4
#define S_  2048
#define D_  1024
#define H_  16
#define HD_ 64

// ---------------------------------------------------------------------------
// Static scratch — pure fp16 everywhere.
// ---------------------------------------------------------------------------
__device__ __align__(16) __half g_xh[3][B_ * S_ * D_];
__device__ __align__(16) __half g_wh[3][H_ * D_ * HD_];
__device__ __align__(16) __half g_woh[D_ * D_];
__device__ __align__(16) __half g_qh[B_*H_*S_*HD_];
__device__ __align__(16) __half g_kh[B_*H_*S_*HD_];
__device__ __align__(16) __half g_vh[B_*H_*S_*HD_];
__device__ __align__(16) __half g_zh[B_ * S_ * D_];
__device__ unsigned g_mpk[B_ * S_ * (S_ / 32)];

// ---------------------------------------------------------------------------
// Helpers
// ---------------------------------------------------------------------------
__device__ __forceinline__ uint32_t pack2h(float x, float y) {
    __half2 t = __floats2half2_rn(x, y);
    return *reinterpret_cast<uint32_t*>(&t);
}
__device__ __forceinline__ float ex2(float x) {
    float y; asm("ex2.approx.f32 %0, %1;" : "=f"(y) : "f"(x)); return y;
}
__device__ __forceinline__ uint32_t smem_u32(const void* p) {
    return (uint32_t)__cvta_generic_to_shared(p);
}
__device__ __forceinline__ void ldsm4(uint32_t r[4], uint32_t a) {
    asm volatile("ldmatrix.sync.aligned.m8n8.x4.shared.b16 {%0,%1,%2,%3}, [%4];"
                 : "=r"(r[0]), "=r"(r[1]), "=r"(r[2]), "=r"(r[3]) : "r"(a));
}
__device__ __forceinline__ void ldsm4t(uint32_t r[4], uint32_t a) {
    asm volatile("ldmatrix.sync.aligned.m8n8.x4.trans.shared.b16 {%0,%1,%2,%3}, [%4];"
                 : "=r"(r[0]), "=r"(r[1]), "=r"(r[2]), "=r"(r[3]) : "r"(a));
}
__device__ __forceinline__ void mma_f16(float c[4], const uint32_t a[4], const uint32_t b[2]) {
    asm volatile(
        "mma.sync.aligned.m16n8k16.row.col.f32.f16.f16.f32 "
        "{%0,%1,%2,%3}, {%4,%5,%6,%7}, {%8,%9}, {%0,%1,%2,%3};\n"
        : "+f"(c[0]), "+f"(c[1]), "+f"(c[2]), "+f"(c[3])
        : "r"(a[0]), "r"(a[1]), "r"(a[2]), "r"(a[3]), "r"(b[0]), "r"(b[1]));
}
__device__ __forceinline__ void cpa16(uint32_t saddr, const void* g) {
    asm volatile("cp.async.cg.shared.global [%0], [%1], 16;" :: "r"(saddr), "l"(g) : "memory");
}
__device__ __forceinline__ void cpa_commit() { asm volatile("cp.async.commit_group;" ::: "memory"); }
__device__ __forceinline__ void cpa_wait0()  { asm volatile("cp.async.wait_group 0;" ::: "memory"); }
__device__ __forceinline__ void cpa_wait1()  { asm volatile("cp.async.wait_group 1;" ::: "memory"); }

// ---------------------------------------------------------------------------
// Fused prep kernel: x-cast (blocks 0..24575), w-cast (..28671), mask (..30719)
// ---------------------------------------------------------------------------
__global__ void prep_kernel(const float* __restrict__ xq, const float* __restrict__ xk,
                            const float* __restrict__ xv,
                            const float* __restrict__ Wq, const float* __restrict__ Wk,
                            const float* __restrict__ Wv, const float* __restrict__ Wo,
                            const int* __restrict__ mask)
{
    const int blk = blockIdx.x;
    if (blk < 24576) {
        const int which = blk >> 13;
        const int i = (blk & 8191) * 256 + threadIdx.x;
        const float* in = (which == 0) ? xq : (which == 1) ? xk : xv;
        float4 v = ((const float4*)in)[i];
        ((uint2*)g_xh[which])[i] = make_uint2(pack2h(v.x, v.y), pack2h(v.z, v.w));
    } else if (blk < 28672) {
        const int r = blk - 24576;
        const int dst = r >> 10;
        const int i = (r & 1023) * 256 + threadIdx.x;
        const float* in = (dst == 0) ? Wq : (dst == 1) ? Wk : (dst == 2) ? Wv : Wo;
        __half* hi = (dst < 3) ? g_wh[dst] : g_woh;
        float4 v = ((const float4*)in)[i];
        ((uint2*)hi)[i] = make_uint2(pack2h(v.x, v.y), pack2h(v.z, v.w));
    } else {
        int i = (blk - 28672) * 256 + threadIdx.x;
        if (i >= B_ * S_ * (S_ / 32)) return;
        const int4* mp = (const int4*)(mask + (long)i * 32);
        unsigned w = 0;
#pragma unroll
        for (int j = 0; j < 8; j++) {
            int4 m = mp[j];
            w |= (unsigned)(m.x != 0) << (j * 4 + 0);
            w |= (unsigned)(m.y != 0) << (j * 4 + 1);
            w |= (unsigned)(m.z != 0) << (j * 4 + 2);
            w |= (unsigned)(m.w != 0) << (j * 4 + 3);
        }
        g_mpk[i] = w;
    }
}

// ---------------------------------------------------------------------------
// GEMM: 128(m) x 128(n) x kdim, k-chunks of 64, 2-stage cp.async pipeline.
// Pure fp16. Stage (35840 B): Ah[128 x 144B(64h)] Bh[64 x 272B(128h)]
// ---------------------------------------------------------------------------
#define G_STG   35840
#define G_BH    18432
#define GEMM_DSM (2 * G_STG)

template<bool SPLIT_OUT>
__device__ __forceinline__ void gemm_body(
    const __half* __restrict__ Agh, int lda, int kdim,
    const __half* __restrict__ Bgh, long bHS, int ldb,
    const float* __restrict__ bias,
    float* __restrict__ outF, int ldoF,
    __half* __restrict__ outH, long outHS)
{
    extern __shared__ uint8_t dyn[];
    const uint32_t sb = smem_u32(dyn);

    const int t = threadIdx.x, lane = t & 31, warp = t >> 5;
    const int wm = warp >> 1, wn = warp & 1;
    const int lr = lane >> 2, lc = lane & 3;
    const int g = lane >> 3, lr8 = lane & 7;

    float c[2][8][4];
#pragma unroll
    for (int i = 0; i < 2; i++)
#pragma unroll
        for (int j = 0; j < 8; j++)
#pragma unroll
            for (int k = 0; k < 4; k++) c[i][j][k] = 0.f;

#define G_ISSUE(stg, k0) do { \
        uint32_t base_ = sb + (stg) * G_STG; \
        _Pragma("unroll") \
        for (int j = 0; j < 4; j++) { \
            int idx = t + j * 256, r = idx >> 3, cc = idx & 7; \
            cpa16(base_ + r * 144 + cc * 16, Agh + (long)r * lda + (k0) + cc * 8); \
        } \
        _Pragma("unroll") \
        for (int j = 0; j < 4; j++) { \
            int idx = t + j * 256, r = idx >> 4, n16 = idx & 15; \
            long src = (long)(n16 >> 3) * bHS + (long)((k0) + r) * ldb + (n16 & 7) * 8; \
            cpa16(base_ + G_BH + r * 272 + n16 * 16, Bgh + src); \
        } \
        cpa_commit(); \
    } while (0)

    G_ISSUE(0, 0);
    const int nchunks = kdim / 64;
    for (int ch = 0; ch < nchunks; ch++) {
        const int s = ch & 1;
        __syncthreads();
        if (ch + 1 < nchunks) { G_ISSUE(1 - s, (ch + 1) * 64); cpa_wait1(); }
        else                  { cpa_wait0(); }
        __syncthreads();

        const uint32_t stb = sb + s * G_STG;
        const uint32_t aBH = stb + (wm * 32 + lr8 + ((g & 1) << 3)) * 144 + ((g >> 1) << 4);
        const uint32_t bBH = stb + G_BH + (lr8 + ((g & 1) << 3)) * 272 + wn * 128 + ((g >> 1) << 4);

#pragma unroll
        for (int ks = 0; ks < 4; ks++) {
            uint32_t ah[2][4];
#pragma unroll
            for (int ma = 0; ma < 2; ma++)
                ldsm4(ah[ma], aBH + ma * 2304 + ks * 32);
#pragma unroll
            for (int np = 0; np < 4; np++) {
                uint32_t bh4[4];
                ldsm4t(bh4, bBH + ks * 4352 + np * 32);
#pragma unroll
                for (int ma = 0; ma < 2; ma++) {
                    mma_f16(c[ma][np * 2],     ah[ma], bh4);
                    mma_f16(c[ma][np * 2 + 1], ah[ma], bh4 + 2);
                }
            }
        }
    }
#undef G_ISSUE

#pragma unroll
    for (int ma = 0; ma < 2; ma++) {
#pragma unroll
        for (int na = 0; na < 8; na++) {
            int r   = wm * 32 + ma * 16 + lr;
            int col = wn * 64 + na * 8 + lc * 2;
            float b0 = bias[col], b1 = bias[col + 1];
            float v00 = c[ma][na][0] + b0, v01 = c[ma][na][1] + b1;
            float v10 = c[ma][na][2] + b0, v11 = c[ma][na][3] + b1;
            if (SPLIT_OUT) {
                int head = col >> 6, e = col & 63;
                __half* ph = outH + head * outHS + (long)r * 64 + e;
                *(uint32_t*)ph            = pack2h(v00, v01);
                *(uint32_t*)(ph + 8 * 64) = pack2h(v10, v11);
            } else {
                *(float2*)(outF + (long)r * ldoF + col)       = make_float2(v00, v01);
                *(float2*)(outF + (long)(r + 8) * ldoF + col) = make_float2(v10, v11);
            }
        }
    }
}

__global__ __launch_bounds__(256, 2) void qkv_gemm(
    const float* __restrict__ bq, const float* __restrict__ bk, const float* __restrict__ bv)
{
    const int which = blockIdx.z;
    const int h0 = blockIdx.x * 2;
    const int b  = blockIdx.y >> 4;
    const int s0 = (blockIdx.y & 15) * 128;

    const __half* Agh = g_xh[which] + ((long)b * S_ + s0) * D_;
    const __half* Bgh = g_wh[which] + (long)h0 * D_ * HD_;
    const float* bias = ((which == 0) ? bq : (which == 1) ? bk : bv) + h0 * HD_;

    long ob = ((long)(b * H_ + h0) * S_ + s0) * HD_;
    __half* oh = ((which == 0) ? g_qh : (which == 1) ? g_kh : g_vh) + ob;

    gemm_body<true>(Agh, D_, D_, Bgh, (long)D_ * HD_, HD_,
                    bias, nullptr, 0, oh, (long)S_ * HD_);
}

__global__ __launch_bounds__(256, 2) void outproj_gemm(
    const float* __restrict__ bo, float* __restrict__ out)
{
    const int n0 = blockIdx.x * 128;
    const long m0 = (long)blockIdx.y * 128;
    gemm_body<false>(g_zh + m0 * D_, D_, D_,
                     g_woh + n0, 64, D_,
                     bo + n0, out + m0 * D_ + n0, D_, nullptr, 0);
}

// ---------------------------------------------------------------------------
// Flash attention: 128 q-rows/block, 256 thr = 8 warps, 128-key staged tiles
// processed as two 64-key halves (registers unchanged). 2-stage cp.async.
// Stage (36864 B): Kh[128x144] Vh[128x144]. Q pre-staged in stage-1 Kh area.
// ---------------------------------------------------------------------------
#define A_STG  36864
#define A_VH   18432
#define ATT_DSM (2 * A_STG)

__global__ __launch_bounds__(256, 2) void attn_kernel()
{
    extern __shared__ uint8_t dyn[];
    const uint32_t sb = smem_u32(dyn);

    const int t = threadIdx.x, lane = t & 31, w = t >> 5;
    const int lr = lane >> 2, lc = lane & 3;
    const int g = lane >> 3, lr8 = lane & 7;
    const int bh = blockIdx.y, b = bh >> 4, h = bh & 15;
    const int q0 = blockIdx.x * 128;

    const __half* qgh = g_qh + ((long)bh * S_ + q0) * HD_;
    const __half* khb = g_kh + (long)bh * S_ * HD_;
    const __half* vhb = g_vh + (long)bh * S_ * HD_;
    const float SC = 0.125f * 1.44269504088896340736f;

    // ---- stage Q [128 rows] into stage-1 Kh area ----
#pragma unroll
    for (int j = 0; j < 4; j++) {
        int idx = t + j * 256, r = idx >> 3, cc = idx & 7;
        cpa16(sb + A_STG + r * 144 + cc * 16, qgh + (long)r * HD_ + cc * 8);
    }
    cpa_commit();
    cpa_wait0();
    __syncthreads();

    uint32_t qh[4][4];
    {
        uint32_t qBH = sb + A_STG + (w * 16 + lr8 + ((g & 1) << 3)) * 144 + ((g >> 1) << 4);
#pragma unroll
        for (int ks = 0; ks < 4; ks++)
            ldsm4(qh[ks], qBH + ks * 32);
    }
    __syncthreads();

#define KV_ISSUE(stg, k0) do { \
        uint32_t base_ = sb + (stg) * A_STG; \
        _Pragma("unroll") \
        for (int j = 0; j < 4; j++) { \
            int idx = t + j * 256, r = idx >> 3, cc = idx & 7; \
            cpa16(base_ + r * 144 + cc * 16, khb + (long)((k0) + r) * HD_ + cc * 8); \
        } \
        _Pragma("unroll") \
        for (int j = 0; j < 4; j++) { \
            int idx = t + j * 256, r = idx >> 3, cc = idx & 7; \
            cpa16(base_ + A_VH + r * 144 + cc * 16, vhb + (long)((k0) + r) * HD_ + cc * 8); \
        } \
        cpa_commit(); \
    } while (0)

    float o[8][4];
#pragma unroll
    for (int i = 0; i < 8; i++)
#pragma unroll
        for (int j = 0; j < 4; j++) o[i][j] = 0.f;
    float lacc[2] = {0.f, 0.f};

    const int NT = S_ / 128;
    KV_ISSUE(0, 0);

    for (int kt = 0; kt < NT; kt++) {
        const int s = kt & 1;
        const int k0 = kt * 128;

        __syncthreads();
        if (kt + 1 < NT) { KV_ISSUE(1 - s, k0 + 128); cpa_wait1(); }
        else             { cpa_wait0(); }
        __syncthreads();

        // mask words for the full 128-key tile
        uint32_t mw[2][4];
#pragma unroll
        for (int i = 0; i < 2; i++) {
            int q = q0 + w * 16 + lr + i * 8;
            const unsigned* mp = g_mpk + ((long)b * S_ + q) * (S_ / 32) + (k0 >> 5);
            mw[i][0] = mp[0]; mw[i][1] = mp[1]; mw[i][2] = mp[2]; mw[i][3] = mp[3];
        }

        const uint32_t stb = sb + s * A_STG;

#pragma unroll
        for (int half = 0; half < 2; half++) {
            const uint32_t kBH = stb + (half * 64 + lr8 + ((g >= 2) << 3)) * 144 + ((g & 1) << 4);
            const uint32_t vBH = stb + A_VH + (half * 64 + lr8 + ((g & 1) << 3)) * 144 + ((g >> 1) << 4);

            // ---- S = Qh Kh^T ----
            float s_[8][4];
#pragma unroll
            for (int i = 0; i < 8; i++)
#pragma unroll
                for (int j = 0; j < 4; j++) s_[i][j] = 0.f;
#pragma unroll
            for (int ks = 0; ks < 4; ks++) {
#pragma unroll
                for (int np = 0; np < 4; np++) {
                    uint32_t kb[4];
                    ldsm4(kb, kBH + np * 2304 + ks * 32);
                    mma_f16(s_[np * 2],     qh[ks], kb);
                    mma_f16(s_[np * 2 + 1], qh[ks], kb + 2);
                }
            }

            // ---- mask + exp2 (fixed max 0) ----
#pragma unroll
            for (int i = 0; i < 2; i++) {
#pragma unroll
                for (int na = 0; na < 8; na++) {
                    uint32_t wbits = mw[i][half * 2 + (na >> 2)];
                    int bit = (na & 3) * 8 + lc * 2;
                    float v0 = ((wbits >> bit) & 1)       ? s_[na][i * 2] * SC     : 0.f;
                    float v1 = ((wbits >> (bit + 1)) & 1) ? s_[na][i * 2 + 1] * SC : 0.f;
                    float p0 = ex2(v0), p1 = ex2(v1);
                    s_[na][i * 2] = p0; s_[na][i * 2 + 1] = p1;
                    lacc[i] += p0 + p1;
                }
            }

            // ---- P -> fp16 A-frags ----
            uint32_t ph[4][4];
#pragma unroll
            for (int ks = 0; ks < 4; ks++) {
                ph[ks][0] = pack2h(s_[2 * ks][0],     s_[2 * ks][1]);
                ph[ks][1] = pack2h(s_[2 * ks][2],     s_[2 * ks][3]);
                ph[ks][2] = pack2h(s_[2 * ks + 1][0], s_[2 * ks + 1][1]);
                ph[ks][3] = pack2h(s_[2 * ks + 1][2], s_[2 * ks + 1][3]);
            }

            // ---- O += P Vh ----
#pragma unroll
            for (int ks = 0; ks < 4; ks++) {
#pragma unroll
                for (int np = 0; np < 4; np++) {
                    uint32_t vb[4];
                    ldsm4t(vb, vBH + ks * 2304 + np * 32);
                    mma_f16(o[np * 2],     ph[ks], vb);
                    mma_f16(o[np * 2 + 1], ph[ks], vb + 2);
                }
            }
        }
    }
#undef KV_ISSUE

#pragma unroll
    for (int i = 0; i < 2; i++) {
        lacc[i] += __shfl_xor_sync(0xffffffffu, lacc[i], 1);
        lacc[i] += __shfl_xor_sync(0xffffffffu, lacc[i], 2);
        float inv = 1.f / lacc[i];
        int q = q0 + w * 16 + lr + i * 8;
        __half* zh = g_zh + ((long)b * S_ + q) * D_ + h * HD_;
#pragma unroll
        for (int na = 0; na < 8; na++) {
            *(uint32_t*)(zh + na * 8 + lc * 2) =
                pack2h(o[na][i * 2] * inv, o[na][i * 2 + 1] * inv);
        }
    }
}

// ---------------------------------------------------------------------------
extern "C" void kernel_launch(void* const* d_in, const int* in_sizes, int n_in,
                              void* d_out, int out_size)
{
    const float* xv   = (const float*)d_in[0];
    const float* xk   = (const float*)d_in[1];
    const float* xq   = (const float*)d_in[2];
    const int*   mask = (const int*)  d_in[3];
    const float* Wq   = (const float*)d_in[4];
    const float* bq   = (const float*)d_in[5];
    const float* Wk   = (const float*)d_in[6];
    const float* bk   = (const float*)d_in[7];
    const float* Wv   = (const float*)d_in[8];
    const float* bv   = (const float*)d_in[9];
    const float* Wo   = (const float*)d_in[10];
    const float* bo   = (const float*)d_in[11];
    float* out = (float*)d_out;

    cudaFuncSetAttribute(qkv_gemm,     cudaFuncAttributeMaxDynamicSharedMemorySize, GEMM_DSM);
    cudaFuncSetAttribute(outproj_gemm, cudaFuncAttributeMaxDynamicSharedMemorySize, GEMM_DSM);
    cudaFuncSetAttribute(attn_kernel,  cudaFuncAttributeMaxDynamicSharedMemorySize, ATT_DSM);

    prep_kernel<<<30720, 256>>>(xq, xk, xv, Wq, Wk, Wv, Wo, mask);
    qkv_gemm<<<dim3(H_ / 2, 64, 3), 256, GEMM_DSM>>>(bq, bk, bv);
    attn_kernel<<<dim3(S_ / 128, B_ * H_), 256, ATT_DSM>>>();
    outproj_gemm<<<dim3(D_ / 128, (B_ * S_) / 128), 256, GEMM_DSM>>>(bo, out);
}